// round 13
// baseline (speedup 1.0000x reference)
#include <cuda_runtime.h>
#include <cuda_fp16.h>
#include <cstdint>

// Problem constants
#define Bdim 4
#define Sdim 2048
#define Cdim 1024
#define NH   16
#define HD   64
#define Mrows (Bdim * Sdim)   // 8192

// ---------------------------------------------------------------------------
// Scratch (__device__ globals; referenced ONLY from device code)
// Q/K/V/att stored GEMM-natural: [m][c] with m = b*S+s, c = h*64+d.
// (fp32->fp16 conversion is folded into the GEMM load paths; no staging copies)
// ---------------------------------------------------------------------------
__device__ __align__(16) __half g_q[Mrows * Cdim];
__device__ __align__(16) __half g_k[Mrows * Cdim];
__device__ __align__(16) __half g_v[Mrows * Cdim];
__device__ __align__(16) __half g_at[Mrows * Cdim];

// ---------------------------------------------------------------------------
// PTX helpers (base sm_103 ISA: cp.async, ldmatrix, mma.sync)
// ---------------------------------------------------------------------------
__device__ __forceinline__ uint32_t smem_u32(const void* p) {
    uint32_t a;
    asm("{ .reg .u64 t; cvta.to.shared.u64 t, %1; cvt.u32.u64 %0, t; }"
        : "=r"(a) : "l"(p));
    return a;
}

#define CP_ASYNC16(sa, ga) \
    asm volatile("cp.async.cg.shared.global [%0], [%1], 16;" :: "r"(sa), "l"(ga) : "memory")
#define CP_COMMIT() asm volatile("cp.async.commit_group;" ::: "memory")
#define CP_WAIT(n)  asm volatile("cp.async.wait_group %0;" :: "n"(n) : "memory")

__device__ __forceinline__ void ldsm_x4(uint32_t* r, uint32_t addr) {
    asm volatile("ldmatrix.sync.aligned.m8n8.x4.shared.b16 {%0,%1,%2,%3}, [%4];"
                 : "=r"(r[0]), "=r"(r[1]), "=r"(r[2]), "=r"(r[3]) : "r"(addr));
}
__device__ __forceinline__ void ldsm_x4t(uint32_t* r, uint32_t addr) {
    asm volatile("ldmatrix.sync.aligned.m8n8.x4.trans.shared.b16 {%0,%1,%2,%3}, [%4];"
                 : "=r"(r[0]), "=r"(r[1]), "=r"(r[2]), "=r"(r[3]) : "r"(addr));
}
__device__ __forceinline__ void mma_f16(float* d, const uint32_t* a, const uint32_t* b) {
    asm volatile("mma.sync.aligned.m16n8k16.row.col.f32.f16.f16.f32 "
                 "{%0,%1,%2,%3}, {%4,%5,%6,%7}, {%8,%9}, {%0,%1,%2,%3};"
                 : "+f"(d[0]), "+f"(d[1]), "+f"(d[2]), "+f"(d[3])
                 : "r"(a[0]), "r"(a[1]), "r"(a[2]), "r"(a[3]), "r"(b[0]), "r"(b[1]));
}

// pack two fp32 -> f16x2 (v0 in low half, v1 in high half)
__device__ __forceinline__ uint32_t pack_f16x2(float v0, float v1) {
    uint32_t r;
    asm("cvt.rn.f16x2.f32 %0, %1, %2;" : "=r"(r) : "f"(v1), "f"(v0));
    return r;
}
// convert 8 consecutive fp32 (two float4) to 8 packed halves
__device__ __forceinline__ uint4 cvt8(float4 a, float4 b) {
    uint4 o;
    o.x = pack_f16x2(a.x, a.y);
    o.y = pack_f16x2(a.z, a.w);
    o.z = pack_f16x2(b.x, b.y);
    o.w = pack_f16x2(b.z, b.w);
    return o;
}

// polynomial exp (no MUFU) — valid for x <= ~0, clamped below -80
__device__ __forceinline__ float fast_exp(float x) {
    x = fmaxf(x, -80.f);
    const float y = x * 1.4426950408889634f;
    const float tt = y + 12582912.f;
    const int   i  = __float_as_int(tt);
    const float n  = tt - 12582912.f;
    const float f  = y - n;
    float p = 0.001333355815f;
    p = fmaf(p, f, 0.009618129842f);
    p = fmaf(p, f, 0.05550410866f);
    p = fmaf(p, f, 0.2402265069f);
    p = fmaf(p, f, 0.69314718056f);
    p = fmaf(p, f, 1.0f);
    return __int_as_float(__float_as_int(p) + (i << 23));
}

// ---------------------------------------------------------------------------
// Shared GEMM compute fragment (CTA 128x128, K stage 32, 8 warps 2(M)x4(N),
// warp tile 64x32). Tiles in smem: ch*2048 + row*16, ch = k chunk (0..3).
// ---------------------------------------------------------------------------
#define STAGE_HB 16384u      // A 8KB + B 8KB per stage
#define NSTAGE   32          // K = 1024 / 32

#define GEMM_COMPUTE(bufb)                                                     \
    {                                                                          \
        const uint32_t bA = (bufb);                                            \
        const uint32_t bB = (bufb) + 8192u;                                    \
        _Pragma("unroll")                                                      \
        for (int k16 = 0; k16 < 2; ++k16) {                                    \
            uint32_t af[4][4];                                                 \
            {                                                                  \
                const int arow = warp_m + (lane & 15);                         \
                const int kc = k16 * 2 + (lane >> 4);                          \
                _Pragma("unroll")                                              \
                for (int tm = 0; tm < 4; ++tm)                                 \
                    ldsm_x4(af[tm], bA + (uint32_t)(kc * 2048 + (arow + tm * 16) * 16)); \
            }                                                                  \
            uint32_t bf[4][2];                                                 \
            {                                                                  \
                const int gg = lane >> 3;                                      \
                const int nr = (lane & 7) + ((gg >> 1) << 3);                  \
                const int kc = k16 * 2 + (gg & 1);                             \
                _Pragma("unroll")                                              \
                for (int half = 0; half < 2; ++half) {                         \
                    const int row = warp_n + half * 16 + nr;                   \
                    uint32_t r4[4];                                            \
                    ldsm_x4(r4, bB + (uint32_t)(kc * 2048 + row * 16));        \
                    bf[half * 2 + 0][0] = r4[0]; bf[half * 2 + 0][1] = r4[1];  \
                    bf[half * 2 + 1][0] = r4[2]; bf[half * 2 + 1][1] = r4[3];  \
                }                                                              \
            }                                                                  \
            _Pragma("unroll")                                                  \
            for (int tm = 0; tm < 4; ++tm)                                     \
                _Pragma("unroll")                                              \
                for (int tn = 0; tn < 4; ++tn)                                 \
                    mma_f16(acc[tm][tn], af[tm], bf[tn]);                      \
        }                                                                      \
    }

// ---- Fused Q + KV projection, fp32 operands converted in-flight.
// grid (8, 64, 3): z=0 Q (scaled 0.125) -> g_q; z=1 K -> g_k; z=2 V -> g_v.
__global__ __launch_bounds__(256)
void gemm_qkv(const float* __restrict__ x, const float* __restrict__ y,
              const float* __restrict__ wq, const float* __restrict__ wkv,
              const float* __restrict__ Wq_b, const float* __restrict__ Wkv_b)
{
    const int z = blockIdx.z;
    const float* Asrc = (z == 0) ? x : y;
    const float* Bsrc = (z == 0) ? wq : wkv;
    const float* bias = (z == 0) ? Wq_b : Wkv_b;
    __half* dst = (z == 0) ? g_q : (z == 1) ? g_k : g_v;
    const int csub = (z == 2) ? 1024 : 0;

    __shared__ __align__(128) char smraw[2 * STAGE_HB];   // 32 KB static
    const uint32_t smb = smem_u32(smraw);

    const int tid = threadIdx.x;
    const int wid = tid >> 5;
    const int lane = tid & 31;
    const int m0 = blockIdx.y * 128;
    const int n0 = ((z == 2) ? 1024 : 0) + blockIdx.x * 128;
    const int warp_m = (wid & 1) * 64;
    const int warp_n = (wid >> 1) * 32;
    const int lrow = tid >> 2;       // 0..63
    const int lch  = tid & 3;        // k chunk

    float acc[4][4][4];
#pragma unroll
    for (int i = 0; i < 4; ++i)
#pragma unroll
        for (int j = 0; j < 4; ++j)
#pragma unroll
            for (int c = 0; c < 4; ++c) acc[i][j][c] = 0.f;

    float4 fa[4], fb[4];
    auto ldg_stage = [&](int s) {
        const int cb = s * 32 + lch * 8;
        const float* pa0 = Asrc + (size_t)(m0 + lrow) * Cdim + cb;
        const float* pa1 = Asrc + (size_t)(m0 + 64 + lrow) * Cdim + cb;
        const float* pb0 = Bsrc + (size_t)(n0 + lrow) * Cdim + cb;
        const float* pb1 = Bsrc + (size_t)(n0 + 64 + lrow) * Cdim + cb;
        fa[0] = *(const float4*)pa0;  fa[1] = *(const float4*)(pa0 + 4);
        fa[2] = *(const float4*)pa1;  fa[3] = *(const float4*)(pa1 + 4);
        fb[0] = *(const float4*)pb0;  fb[1] = *(const float4*)(pb0 + 4);
        fb[2] = *(const float4*)pb1;  fb[3] = *(const float4*)(pb1 + 4);
    };
    auto sts_stage = [&](int s) {
        char* buf = smraw + (size_t)(s & 1) * STAGE_HB;
        *(uint4*)(buf + lch * 2048 + lrow * 16)          = cvt8(fa[0], fa[1]);
        *(uint4*)(buf + lch * 2048 + (64 + lrow) * 16)   = cvt8(fa[2], fa[3]);
        *(uint4*)(buf + 8192 + lch * 2048 + lrow * 16)        = cvt8(fb[0], fb[1]);
        *(uint4*)(buf + 8192 + lch * 2048 + (64 + lrow) * 16) = cvt8(fb[2], fb[3]);
    };

    ldg_stage(0);
    sts_stage(0);
    __syncthreads();

    for (int s = 0; s < NSTAGE; ++s) {
        if (s + 1 < NSTAGE) ldg_stage(s + 1);
        GEMM_COMPUTE(smb + (uint32_t)(s & 1) * STAGE_HB)
        if (s + 1 < NSTAGE) sts_stage(s + 1);
        __syncthreads();
    }

    const float qscale = (z == 0) ? 0.125f : 1.0f;
#pragma unroll
    for (int tm = 0; tm < 4; ++tm) {
#pragma unroll
        for (int tn = 0; tn < 4; ++tn) {
            const int rbase = m0 + warp_m + tm * 16 + (lane >> 2);
            const int c = n0 + warp_n + tn * 8 + (lane & 3) * 2;
            const float b0 = bias[c], b1 = bias[c + 1];
            const int cc = c - csub;
#pragma unroll
            for (int half = 0; half < 2; ++half) {
                const int m = rbase + half * 8;
                const float v0 = (acc[tm][tn][half * 2 + 0] + b0) * qscale;
                const float v1 = (acc[tm][tn][half * 2 + 1] + b1) * qscale;
                *(uint32_t*)(dst + (size_t)m * Cdim + cc) = pack_f16x2(v0, v1);
            }
        }
    }
}

// ---- O projection: out = g_at @ Wo^T + b (A fp16 via cp.async, Wo fp32
// converted in-flight). grid (8, 64), fp32 out [m][n].
__global__ __launch_bounds__(256)
void gemm_o(const float* __restrict__ wo, const float* __restrict__ Wo_b,
            float* __restrict__ out)
{
    __shared__ __align__(128) char smraw[2 * STAGE_HB];
    const uint32_t smb = smem_u32(smraw);

    const int tid = threadIdx.x;
    const int wid = tid >> 5;
    const int lane = tid & 31;
    const int m0 = blockIdx.y * 128;
    const int n0 = blockIdx.x * 128;
    const int warp_m = (wid & 1) * 64;
    const int warp_n = (wid >> 1) * 32;
    const int lrow = tid >> 2;
    const int lch  = tid & 3;

    float acc[4][4][4];
#pragma unroll
    for (int i = 0; i < 4; ++i)
#pragma unroll
        for (int j = 0; j < 4; ++j)
#pragma unroll
            for (int c = 0; c < 4; ++c) acc[i][j][c] = 0.f;

    float4 fb[4];
    auto cpa_stage = [&](int s) {      // A (g_at, fp16) via cp.async
        const int cb = s * 32 + lch * 8;
        const uint32_t bufb = smb + (uint32_t)(s & 1) * STAGE_HB;
        CP_ASYNC16(bufb + (uint32_t)(lch * 2048 + lrow * 16),
                   g_at + (size_t)(m0 + lrow) * Cdim + cb);
        CP_ASYNC16(bufb + (uint32_t)(lch * 2048 + (64 + lrow) * 16),
                   g_at + (size_t)(m0 + 64 + lrow) * Cdim + cb);
        CP_COMMIT();
    };
    auto ldgb_stage = [&](int s) {     // B (wo, fp32) via LDG
        const int cb = s * 32 + lch * 8;
        const float* pb0 = wo + (size_t)(n0 + lrow) * Cdim + cb;
        const float* pb1 = wo + (size_t)(n0 + 64 + lrow) * Cdim + cb;
        fb[0] = *(const float4*)pb0;  fb[1] = *(const float4*)(pb0 + 4);
        fb[2] = *(const float4*)pb1;  fb[3] = *(const float4*)(pb1 + 4);
    };
    auto stsb_stage = [&](int s) {
        char* buf = smraw + (size_t)(s & 1) * STAGE_HB + 8192;
        *(uint4*)(buf + lch * 2048 + lrow * 16)        = cvt8(fb[0], fb[1]);
        *(uint4*)(buf + lch * 2048 + (64 + lrow) * 16) = cvt8(fb[2], fb[3]);
    };

    cpa_stage(0);
    ldgb_stage(0);
    stsb_stage(0);
    CP_WAIT(0);
    __syncthreads();

    for (int s = 0; s < NSTAGE; ++s) {
        if (s + 1 < NSTAGE) { cpa_stage(s + 1); ldgb_stage(s + 1); }
        GEMM_COMPUTE(smb + (uint32_t)(s & 1) * STAGE_HB)
        if (s + 1 < NSTAGE) stsb_stage(s + 1);
        CP_WAIT(0);
        __syncthreads();
    }

#pragma unroll
    for (int tm = 0; tm < 4; ++tm) {
#pragma unroll
        for (int tn = 0; tn < 4; ++tn) {
            const int rbase = m0 + warp_m + tm * 16 + (lane >> 2);
            const int c = n0 + warp_n + tn * 8 + (lane & 3) * 2;
            const float b0 = Wo_b[c], b1 = Wo_b[c + 1];
#pragma unroll
            for (int half = 0; half < 2; ++half) {
                const int m = rbase + half * 8;
                float2 o;
                o.x = acc[tm][tn][half * 2 + 0] + b0;
                o.y = acc[tm][tn][half * 2 + 1] + b1;
                *(float2*)(out + (size_t)m * Cdim + c) = o;
            }
        }
    }
}

// ---------------------------------------------------------------------------
// Tensor-core fp16 flash attention (R11 version: 2 buffers, staggered K/V,
// maskadd in smem, triangle pairing). Q/K/V in [m][h*64+d] layout.
// grid (16, NH, B); CTA does q-block bx AND q-block (31-bx): 33 tiles each.
// ---------------------------------------------------------------------------
__global__ __launch_bounds__(128)
void attn_tc(const unsigned char* __restrict__ mask)
{
    __shared__ __align__(128) unsigned char kvraw[16384];
    __shared__ __align__(8) float maskadd[64];

    const int h  = blockIdx.y;
    const int b  = blockIdx.z;
    const int tid = threadIdx.x;
    const int wid = tid >> 5;
    const int lane = tid & 31;
    const int g = lane >> 2, t = lane & 3;

    const uint32_t smb = smem_u32(kvraw);
    const uint32_t kb = smb;
    const uint32_t vb = smb + 8192;

    const size_t mb0 = (size_t)b * Sdim;
    const __half* K = g_k + mb0 * Cdim + h * HD;
    const __half* V = g_v + mb0 * Cdim + h * HD;
    const unsigned char* mrow = mask + mb0;

    auto load_k = [&](int k0) {
#pragma unroll
        for (int i2 = 0; i2 < 4; ++i2) {
            const int e = i2 * 128 + tid;
            const int row = e >> 3, ch = e & 7;
            CP_ASYNC16(kb + (uint32_t)(ch * 1024 + row * 16),
                       K + (size_t)(k0 + row) * Cdim + ch * 8);
        }
        CP_COMMIT();
    };
    auto load_v = [&](int k0) {
#pragma unroll
        for (int i2 = 0; i2 < 4; ++i2) {
            const int e = i2 * 128 + tid;
            const int row = e >> 3, ch = e & 7;
            CP_ASYNC16(vb + (uint32_t)(ch * 1024 + row * 16),
                       V + (size_t)(k0 + row) * Cdim + ch * 8);
        }
        CP_COMMIT();
    };

#pragma unroll 1
    for (int sub = 0; sub < 2; ++sub) {
        const int qblk = (sub == 0) ? (int)blockIdx.x
                                    : (Sdim / 64 - 1 - (int)blockIdx.x);
        const int q0 = qblk * 64;
        const int nt = qblk + 1;
        const int qg = q0 + wid * 16 + g;
        const __half* Q = g_q + (mb0 + q0) * Cdim + h * HD;

        // ---- stage Q through K buffer, load fragments
#pragma unroll
        for (int i2 = 0; i2 < 4; ++i2) {
            const int e = i2 * 128 + tid;
            const int row = e >> 3, ch = e & 7;
            CP_ASYNC16(kb + (uint32_t)(ch * 1024 + row * 16),
                       Q + (size_t)row * Cdim + ch * 8);
        }
        CP_COMMIT(); CP_WAIT(0);
        __syncthreads();

        uint32_t qf[4][4];
        {
            const int qrow = wid * 16 + (lane & 15);
#pragma unroll
            for (int ks = 0; ks < 4; ++ks)
                ldsm_x4(qf[ks], kb + (uint32_t)((2 * ks + (lane >> 4)) * 1024 + qrow * 16));
        }
        __syncthreads();

        float oacc[8][4];
#pragma unroll
        for (int j = 0; j < 8; ++j)
#pragma unroll
            for (int c = 0; c < 4; ++c) oacc[j][c] = 0.f;
        float m0 = -1e30f, m1 = -1e30f, l0 = 0.f, l1 = 0.f;

        load_k(0);

        for (int it = 0; it < nt; ++it) {
            const int k0 = it * 64;

            CP_WAIT(0);                      // K_it resident
            if (tid < 64)
                maskadd[tid] = mrow[k0 + tid] ? -1e30f : 0.f;
            __syncthreads();
            load_v(k0);                      // V_it loads under S compute

            float sacc[8][4];
#pragma unroll
            for (int j = 0; j < 8; ++j)
#pragma unroll
                for (int c = 0; c < 4; ++c) sacc[j][c] = 0.f;

#pragma unroll
            for (int ks = 0; ks < 4; ++ks) {
                uint32_t kf[8][2];
#pragma unroll
                for (int grp = 0; grp < 4; ++grp) {
                    const uint32_t a = (uint32_t)((2 * ks + (lane >> 4)) * 1024 +
                                                  (grp * 16 + (lane & 15)) * 16);
                    uint32_t r[4];
                    ldsm_x4(r, kb + a);
                    kf[2*grp][0] = r[0]; kf[2*grp][1] = r[2];
                    kf[2*grp+1][0] = r[1]; kf[2*grp+1][1] = r[3];
                }
#pragma unroll
                for (int j = 0; j < 8; ++j)
                    mma_f16(sacc[j], qf[ks], kf[j]);
            }

            const bool diag = (k0 == q0);
            float mx0 = -1e30f, mx1 = -1e30f;
#pragma unroll
            for (int j = 0; j < 8; ++j) {
                const float2 ma = *(const float2*)&maskadd[8 * j + 2 * t];
                float s0 = sacc[j][0] + ma.x;
                float s1 = sacc[j][1] + ma.y;
                float s2 = sacc[j][2] + ma.x;
                float s3 = sacc[j][3] + ma.y;
                if (diag) {
                    const int key = k0 + 8 * j + 2 * t;
                    if (key     > qg)     s0 = -1e30f;
                    if (key + 1 > qg)     s1 = -1e30f;
                    if (key     > qg + 8) s2 = -1e30f;
                    if (key + 1 > qg + 8) s3 = -1e30f;
                }
                sacc[j][0] = s0; sacc[j][1] = s1; sacc[j][2] = s2; sacc[j][3] = s3;
                mx0 = fmaxf(mx0, fmaxf(s0, s1));
                mx1 = fmaxf(mx1, fmaxf(s2, s3));
            }
            mx0 = fmaxf(mx0, __shfl_xor_sync(0xFFFFFFFFu, mx0, 1));
            mx0 = fmaxf(mx0, __shfl_xor_sync(0xFFFFFFFFu, mx0, 2));
            mx1 = fmaxf(mx1, __shfl_xor_sync(0xFFFFFFFFu, mx1, 1));
            mx1 = fmaxf(mx1, __shfl_xor_sync(0xFFFFFFFFu, mx1, 2));
            const float mn0 = fmaxf(m0, mx0), mn1 = fmaxf(m1, mx1);
            const float cr0 = fast_exp(m0 - mn0), cr1 = fast_exp(m1 - mn1);
            m0 = mn0; m1 = mn1;
            l0 *= cr0; l1 *= cr1;
#pragma unroll
            for (int j = 0; j < 8; ++j) {
                oacc[j][0] *= cr0; oacc[j][1] *= cr0;
                oacc[j][2] *= cr1; oacc[j][3] *= cr1;
            }

            float sum0 = 0.f, sum1 = 0.f;
            uint32_t pf[4][4];
#pragma unroll
            for (int j = 0; j < 8; ++j) {
                const float p0 = fast_exp(sacc[j][0] - mn0);
                const float p1 = fast_exp(sacc[j][1] - mn0);
                const float p2 = fast_exp(sacc[j][2] - mn1);
                const float p3 = fast_exp(sacc[j][3] - mn1);
                sum0 += p0 + p1; sum1 += p2 + p3;
                const int kk = j >> 1, sl = (j & 1) * 2;
                pf[kk][sl + 0] = pack_f16x2(p0, p1);
                pf[kk][sl + 1] = pack_f16x2(p2, p3);
            }
            sum0 += __shfl_xor_sync(0xFFFFFFFFu, sum0, 1);
            sum0 += __shfl_xor_sync(0xFFFFFFFFu, sum0, 2);
            sum1 += __shfl_xor_sync(0xFFFFFFFFu, sum1, 1);
            sum1 += __shfl_xor_sync(0xFFFFFFFFu, sum1, 2);
            l0 += sum0; l1 += sum1;

            CP_WAIT(0);                      // V_it resident
            __syncthreads();
            if (it + 1 < nt) load_k(k0 + 64);

#pragma unroll
            for (int kp = 0; kp < 4; ++kp) {
                uint32_t vf[8][2];
#pragma unroll
                for (int db = 0; db < 4; ++db) {
                    const uint32_t a = (uint32_t)((2 * db + (lane >> 4)) * 1024 +
                                                  (kp * 16 + (lane & 15)) * 16);
                    uint32_t r[4];
                    ldsm_x4t(r, vb + a);
                    vf[2*db][0] = r[0]; vf[2*db][1] = r[1];
                    vf[2*db+1][0] = r[2]; vf[2*db+1][1] = r[3];
                }
#pragma unroll
                for (int j = 0; j < 8; ++j)
                    mma_f16(oacc[j], pf[kp], vf[j]);
            }
        }

        const float inv0 = 1.f / l0;
        const float inv1 = 1.f / l1;
        __half* o0p = g_at + (mb0 + qg) * Cdim + h * HD;
        __half* o1p = o0p + 8 * Cdim;
#pragma unroll
        for (int j = 0; j < 8; ++j) {
            const int d = 8 * j + 2 * t;
            *(uint32_t*)(o0p + d) = pack_f16x2(oacc[j][0] * inv0, oacc[j][1] * inv0);
            *(uint32_t*)(o1p + d) = pack_f16x2(oacc[j][2] * inv1, oacc[j][3] * inv1);
        }
        __syncthreads();   // buffer reuse safety across sub iterations
    }
}

// ---------------------------------------------------------------------------
extern "C" void kernel_launch(void* const* d_in, const int* in_sizes, int n_in,
                              void* d_out, int out_size)
{
    const float* x     = (const float*)d_in[0];
    const float* y     = (const float*)d_in[1];
    const unsigned char* mask = (const unsigned char*)d_in[2];
    const float* Wq_w  = (const float*)d_in[3];
    const float* Wq_b  = (const float*)d_in[4];
    const float* Wkv_w = (const float*)d_in[5];
    const float* Wkv_b = (const float*)d_in[6];
    const float* Wo_w  = (const float*)d_in[7];
    const float* Wo_b  = (const float*)d_in[8];
    float* out = (float*)d_out;

    gemm_qkv<<<dim3(8, 64, 3), 256>>>(x, y, Wq_w, Wkv_w, Wq_b, Wkv_b);
    attn_tc<<<dim3(Sdim / 128, NH, Bdim), 128>>>(mask);
    gemm_o<<<dim3(8, 64), 256>>>(Wo_w, Wo_b, out);
}

// round 14
// speedup vs baseline: 1.0962x; 1.0962x over previous
#include <cuda_runtime.h>
#include <cuda_fp16.h>
#include <cstdint>

// Problem constants
#define Bdim 4
#define Sdim 2048
#define Cdim 1024
#define NH   16
#define HD   64
#define Mrows (Bdim * Sdim)   // 8192

// ---------------------------------------------------------------------------
// Scratch (__device__ globals; referenced ONLY from device code)
// Q/K/V/att stored GEMM-natural: [m][c] with m = b*S+s, c = h*64+d.
// ---------------------------------------------------------------------------
__device__ __align__(16) __half g_q[Mrows * Cdim];
__device__ __align__(16) __half g_k[Mrows * Cdim];
__device__ __align__(16) __half g_v[Mrows * Cdim];

__device__ __align__(16) __half g_x[Mrows * Cdim];
__device__ __align__(16) __half g_y[Mrows * Cdim];
__device__ __align__(16) __half g_at[Mrows * Cdim];
__device__ __align__(16) __half g_wq[Cdim * Cdim];
__device__ __align__(16) __half g_wkv[2 * Cdim * Cdim];
__device__ __align__(16) __half g_wo[Cdim * Cdim];

// ---------------------------------------------------------------------------
// PTX helpers (base sm_103 ISA: cp.async, ldmatrix, mma.sync)
// ---------------------------------------------------------------------------
__device__ __forceinline__ uint32_t smem_u32(const void* p) {
    uint32_t a;
    asm("{ .reg .u64 t; cvta.to.shared.u64 t, %1; cvt.u32.u64 %0, t; }"
        : "=r"(a) : "l"(p));
    return a;
}

#define CP_ASYNC16(sa, ga) \
    asm volatile("cp.async.cg.shared.global [%0], [%1], 16;" :: "r"(sa), "l"(ga) : "memory")
#define CP_COMMIT() asm volatile("cp.async.commit_group;" ::: "memory")
#define CP_WAIT(n)  asm volatile("cp.async.wait_group %0;" :: "n"(n) : "memory")

__device__ __forceinline__ void ldsm_x4(uint32_t* r, uint32_t addr) {
    asm volatile("ldmatrix.sync.aligned.m8n8.x4.shared.b16 {%0,%1,%2,%3}, [%4];"
                 : "=r"(r[0]), "=r"(r[1]), "=r"(r[2]), "=r"(r[3]) : "r"(addr));
}
__device__ __forceinline__ void ldsm_x4t(uint32_t* r, uint32_t addr) {
    asm volatile("ldmatrix.sync.aligned.m8n8.x4.trans.shared.b16 {%0,%1,%2,%3}, [%4];"
                 : "=r"(r[0]), "=r"(r[1]), "=r"(r[2]), "=r"(r[3]) : "r"(addr));
}
__device__ __forceinline__ void mma_f16(float* d, const uint32_t* a, const uint32_t* b) {
    asm volatile("mma.sync.aligned.m16n8k16.row.col.f32.f16.f16.f32 "
                 "{%0,%1,%2,%3}, {%4,%5,%6,%7}, {%8,%9}, {%0,%1,%2,%3};"
                 : "+f"(d[0]), "+f"(d[1]), "+f"(d[2]), "+f"(d[3])
                 : "r"(a[0]), "r"(a[1]), "r"(a[2]), "r"(a[3]), "r"(b[0]), "r"(b[1]));
}

// pack two fp32 -> f16x2 (v0 in low half, v1 in high half)
__device__ __forceinline__ uint32_t pack_f16x2(float v0, float v1) {
    uint32_t r;
    asm("cvt.rn.f16x2.f32 %0, %1, %2;" : "=r"(r) : "f"(v1), "f"(v0));
    return r;
}

// polynomial exp (no MUFU) — valid for x <= ~0, clamped below -80
__device__ __forceinline__ float fast_exp(float x) {
    x = fmaxf(x, -80.f);
    const float y = x * 1.4426950408889634f;
    const float tt = y + 12582912.f;
    const int   i  = __float_as_int(tt);
    const float n  = tt - 12582912.f;
    const float f  = y - n;
    float p = 0.001333355815f;
    p = fmaf(p, f, 0.009618129842f);
    p = fmaf(p, f, 0.05550410866f);
    p = fmaf(p, f, 0.2402265069f);
    p = fmaf(p, f, 0.69314718056f);
    p = fmaf(p, f, 1.0f);
    return __int_as_float(__float_as_int(p) + (i << 23));
}

// ---------------------------------------------------------------------------
// Single fused fp32 -> fp16 convert, 8 elements per thread (uint4 stores).
// ---------------------------------------------------------------------------
#define NX8  (Mrows * Cdim / 8)
#define NW8  (Cdim * Cdim / 8)
#define NKV8 (2 * Cdim * Cdim / 8)
#define NTOT8 (2 * NX8 + 2 * NW8 + NKV8)

__global__ __launch_bounds__(256)
void convert_all(const float4* __restrict__ x, const float4* __restrict__ y,
                 const float4* __restrict__ wq, const float4* __restrict__ wkv,
                 const float4* __restrict__ wo)
{
    const int i = blockIdx.x * 256 + threadIdx.x;
    const float4* src;
    __half* dst;
    int si;
    if (i < NX8)                        { src = x;   dst = g_x;   si = i; }
    else if (i < 2 * NX8)               { src = y;   dst = g_y;   si = i - NX8; }
    else if (i < 2 * NX8 + NW8)         { src = wq;  dst = g_wq;  si = i - 2 * NX8; }
    else if (i < 2 * NX8 + NW8 + NKV8)  { src = wkv; dst = g_wkv; si = i - 2 * NX8 - NW8; }
    else                                { src = wo;  dst = g_wo;  si = i - 2 * NX8 - NW8 - NKV8; }
    const float4 v0 = src[2 * si];
    const float4 v1 = src[2 * si + 1];
    uint4 o;
    o.x = pack_f16x2(v0.x, v0.y);
    o.y = pack_f16x2(v0.z, v0.w);
    o.z = pack_f16x2(v1.x, v1.y);
    o.w = pack_f16x2(v1.z, v1.w);
    ((uint4*)dst)[si] = o;
}

// ---------------------------------------------------------------------------
// gemm_qkv: CTA tile 128x128 (2 CTAs/SM for better tail overlap), K stage 32,
// 2-stage cp.async, 32KB static smem. 8 warps 2(M)x4(N), warp tile 64x32.
// Smem tiles: ch*2048 + row*16 (128 rows each for A and B).
// grid (8, 64, 3): z=0 Q (scaled 0.125) -> g_q; z=1 K -> g_k; z=2 V -> g_v.
// Coalesced [m][c] fp16 epilogue.
// ---------------------------------------------------------------------------
#define QKV_STAGE 16384u     // A 8KB + B 8KB
#define NSTAGE    32         // K = 1024 / 32

__global__ __launch_bounds__(256)
void gemm_qkv(const float* __restrict__ Wq_b, const float* __restrict__ Wkv_b)
{
    const int z = blockIdx.z;
    const __half* A = (z == 0) ? g_x : g_y;
    const __half* B = (z == 0) ? g_wq : g_wkv;
    const float* bias = (z == 0) ? Wq_b : Wkv_b;
    __half* dst = (z == 0) ? g_q : (z == 1) ? g_k : g_v;
    const int csub = (z == 2) ? 1024 : 0;

    __shared__ __align__(128) char smraw[2 * QKV_STAGE];   // 32 KB static
    const uint32_t smb = smem_u32(smraw);

    const int tid = threadIdx.x;
    const int wid = tid >> 5;
    const int lane = tid & 31;
    const int m0 = blockIdx.y * 128;
    const int n0 = ((z == 2) ? 1024 : 0) + blockIdx.x * 128;
    const int warp_m = (wid & 1) * 64;
    const int warp_n = (wid >> 1) * 32;
    const int lrow = tid >> 1;       // 0..127
    const int lch  = tid & 1;        // chunk pair

    float acc[4][4][4];
#pragma unroll
    for (int i = 0; i < 4; ++i)
#pragma unroll
        for (int j = 0; j < 4; ++j)
#pragma unroll
            for (int c = 0; c < 4; ++c) acc[i][j][c] = 0.f;

    auto load_stage = [&](int s) {
        const int k0g = s * 32;
        const uint32_t bufb = smb + (uint32_t)(s & 1) * QKV_STAGE;
        // A: 128 rows x 4 chunks; 256 thr x 2 = 512 chunks total (A then B)
#pragma unroll
        for (int i = 0; i < 2; ++i) {
            const int e = i * 256 + tid;          // 0..511
            const int row = e >> 2, ch = e & 3;
            CP_ASYNC16(bufb + (uint32_t)(ch * 2048 + row * 16),
                       A + (size_t)(m0 + row) * Cdim + k0g + ch * 8);
        }
#pragma unroll
        for (int i = 0; i < 2; ++i) {
            const int e = i * 256 + tid;
            const int row = e >> 2, ch = e & 3;
            CP_ASYNC16(bufb + 8192u + (uint32_t)(ch * 2048 + row * 16),
                       B + (size_t)(n0 + row) * Cdim + k0g + ch * 8);
        }
        CP_COMMIT();
    };

    load_stage(0);

    for (int s = 0; s < NSTAGE; ++s) {
        CP_WAIT(0);
        __syncthreads();
        if (s + 1 < NSTAGE) load_stage(s + 1);

        const uint32_t bufb = smb + (uint32_t)(s & 1) * QKV_STAGE;
        const uint32_t bA = bufb;
        const uint32_t bB = bufb + 8192u;

#pragma unroll
        for (int k16 = 0; k16 < 2; ++k16) {
            uint32_t af[4][4];
            {
                const int arow = warp_m + (lane & 15);
                const int kc = k16 * 2 + (lane >> 4);
#pragma unroll
                for (int tm = 0; tm < 4; ++tm)
                    ldsm_x4(af[tm], bA + (uint32_t)(kc * 2048 + (arow + tm * 16) * 16));
            }
            uint32_t bf[4][2];
            {
                const int gg = lane >> 3;
                const int nr = (lane & 7) + ((gg >> 1) << 3);
                const int kc = k16 * 2 + (gg & 1);
#pragma unroll
                for (int half = 0; half < 2; ++half) {
                    const int row = warp_n + half * 16 + nr;
                    uint32_t r4[4];
                    ldsm_x4(r4, bB + (uint32_t)(kc * 2048 + row * 16));
                    bf[half * 2 + 0][0] = r4[0]; bf[half * 2 + 0][1] = r4[1];
                    bf[half * 2 + 1][0] = r4[2]; bf[half * 2 + 1][1] = r4[3];
                }
            }
#pragma unroll
            for (int tm = 0; tm < 4; ++tm)
#pragma unroll
                for (int tn = 0; tn < 4; ++tn)
                    mma_f16(acc[tm][tn], af[tm], bf[tn]);
        }
        __syncthreads();
    }

    const float qscale = (z == 0) ? 0.125f : 1.0f;
#pragma unroll
    for (int tm = 0; tm < 4; ++tm) {
#pragma unroll
        for (int tn = 0; tn < 4; ++tn) {
            const int rbase = m0 + warp_m + tm * 16 + (lane >> 2);
            const int c = n0 + warp_n + tn * 8 + (lane & 3) * 2;
            const float b0 = bias[c], b1 = bias[c + 1];
            const int cc = c - csub;
#pragma unroll
            for (int half = 0; half < 2; ++half) {
                const int m = rbase + half * 8;
                const float v0 = (acc[tm][tn][half * 2 + 0] + b0) * qscale;
                const float v1 = (acc[tm][tn][half * 2 + 1] + b1) * qscale;
                *(uint32_t*)(dst + (size_t)m * Cdim + cc) = pack_f16x2(v0, v1);
            }
        }
    }
}

// ---------------------------------------------------------------------------
// gemm_o: CTA tile 128x256 (measured best for this shape), K stage 32,
// 2-stage cp.async, 48KB static smem. 8 warps 2(M)x4(N), warp tile 64x64.
// out = g_at @ Wo^T + b, fp32 [m][n]. grid (4, 64).
// ---------------------------------------------------------------------------
#define A_TILE  8192u
#define STAGE_B 24576u

__global__ __launch_bounds__(256)
void gemm_o(const float* __restrict__ Wo_b, float* __restrict__ out)
{
    __shared__ __align__(128) char smraw[2 * STAGE_B];
    const uint32_t smb = smem_u32(smraw);

    const int tid = threadIdx.x;
    const int wid = tid >> 5;
    const int lane = tid & 31;
    const int m0 = blockIdx.y * 128;
    const int n0 = blockIdx.x * 256;
    const int warp_m = (wid & 1) * 64;
    const int warp_n = (wid >> 1) * 64;

    float acc[4][8][4];
#pragma unroll
    for (int i = 0; i < 4; ++i)
#pragma unroll
        for (int j = 0; j < 8; ++j)
#pragma unroll
            for (int c = 0; c < 4; ++c) acc[i][j][c] = 0.f;

    auto load_stage = [&](int s) {
        const int k0g = s * 32;
        const uint32_t bufb = smb + (uint32_t)(s & 1) * STAGE_B;
#pragma unroll
        for (int i = 0; i < 2; ++i) {
            const int e = i * 256 + tid;
            const int row = e >> 2, ch = e & 3;
            CP_ASYNC16(bufb + (uint32_t)(ch * 2048 + row * 16),
                       g_at + (size_t)(m0 + row) * Cdim + k0g + ch * 8);
        }
#pragma unroll
        for (int i = 0; i < 4; ++i) {
            const int e = i * 256 + tid;
            const int row = e >> 2, ch = e & 3;
            CP_ASYNC16(bufb + A_TILE + (uint32_t)(ch * 4096 + row * 16),
                       g_wo + (size_t)(n0 + row) * Cdim + k0g + ch * 8);
        }
        CP_COMMIT();
    };

    load_stage(0);

    for (int s = 0; s < NSTAGE; ++s) {
        CP_WAIT(0);
        __syncthreads();
        if (s + 1 < NSTAGE) load_stage(s + 1);

        const uint32_t bufb = smb + (uint32_t)(s & 1) * STAGE_B;
        const uint32_t bA = bufb;
        const uint32_t bB = bufb + A_TILE;

#pragma unroll
        for (int k16 = 0; k16 < 2; ++k16) {
            uint32_t af[4][4];
            {
                const int arow = warp_m + (lane & 15);
                const int kc = k16 * 2 + (lane >> 4);
#pragma unroll
                for (int tm = 0; tm < 4; ++tm)
                    ldsm_x4(af[tm], bA + (uint32_t)(kc * 2048 + (arow + tm * 16) * 16));
            }
            uint32_t bf[8][2];
            {
                const int gg = lane >> 3;
                const int nr = (lane & 7) + ((gg >> 1) << 3);
                const int kc = k16 * 2 + (gg & 1);
#pragma unroll
                for (int half = 0; half < 4; ++half) {
                    const int row = warp_n + half * 16 + nr;
                    uint32_t r4[4];
                    ldsm_x4(r4, bB + (uint32_t)(kc * 4096 + row * 16));
                    bf[half * 2 + 0][0] = r4[0]; bf[half * 2 + 0][1] = r4[1];
                    bf[half * 2 + 1][0] = r4[2]; bf[half * 2 + 1][1] = r4[3];
                }
            }
#pragma unroll
            for (int tm = 0; tm < 4; ++tm)
#pragma unroll
                for (int tn = 0; tn < 8; ++tn)
                    mma_f16(acc[tm][tn], af[tm], bf[tn]);
        }
        __syncthreads();
    }

#pragma unroll
    for (int tm = 0; tm < 4; ++tm) {
#pragma unroll
        for (int tn = 0; tn < 8; ++tn) {
            const int rbase = m0 + warp_m + tm * 16 + (lane >> 2);
            const int c = n0 + warp_n + tn * 8 + (lane & 3) * 2;
            const float b0 = Wo_b[c], b1 = Wo_b[c + 1];
#pragma unroll
            for (int half = 0; half < 2; ++half) {
                const int m = rbase + half * 8;
                float2 o;
                o.x = acc[tm][tn][half * 2 + 0] + b0;
                o.y = acc[tm][tn][half * 2 + 1] + b1;
                *(float2*)(out + (size_t)m * Cdim + c) = o;
            }
        }
    }
}

// ---------------------------------------------------------------------------
// Tensor-core fp16 flash attention (R11 version: 2 buffers, staggered K/V,
// maskadd in smem, triangle pairing). Q/K/V in [m][h*64+d] layout.
// grid (16, NH, B); CTA does q-block bx AND q-block (31-bx): 33 tiles each.
// ---------------------------------------------------------------------------
__global__ __launch_bounds__(128)
void attn_tc(const unsigned char* __restrict__ mask)
{
    __shared__ __align__(128) unsigned char kvraw[16384];
    __shared__ __align__(8) float maskadd[64];

    const int h  = blockIdx.y;
    const int b  = blockIdx.z;
    const int tid = threadIdx.x;
    const int wid = tid >> 5;
    const int lane = tid & 31;
    const int g = lane >> 2, t = lane & 3;

    const uint32_t smb = smem_u32(kvraw);
    const uint32_t kb = smb;
    const uint32_t vb = smb + 8192;

    const size_t mb0 = (size_t)b * Sdim;
    const __half* K = g_k + mb0 * Cdim + h * HD;
    const __half* V = g_v + mb0 * Cdim + h * HD;
    const unsigned char* mrow = mask + mb0;

    auto load_k = [&](int k0) {
#pragma unroll
        for (int i2 = 0; i2 < 4; ++i2) {
            const int e = i2 * 128 + tid;
            const int row = e >> 3, ch = e & 7;
            CP_ASYNC16(kb + (uint32_t)(ch * 1024 + row * 16),
                       K + (size_t)(k0 + row) * Cdim + ch * 8);
        }
        CP_COMMIT();
    };
    auto load_v = [&](int k0) {
#pragma unroll
        for (int i2 = 0; i2 < 4; ++i2) {
            const int e = i2 * 128 + tid;
            const int row = e >> 3, ch = e & 7;
            CP_ASYNC16(vb + (uint32_t)(ch * 1024 + row * 16),
                       V + (size_t)(k0 + row) * Cdim + ch * 8);
        }
        CP_COMMIT();
    };

#pragma unroll 1
    for (int sub = 0; sub < 2; ++sub) {
        const int qblk = (sub == 0) ? (int)blockIdx.x
                                    : (Sdim / 64 - 1 - (int)blockIdx.x);
        const int q0 = qblk * 64;
        const int nt = qblk + 1;
        const int qg = q0 + wid * 16 + g;
        const __half* Q = g_q + (mb0 + q0) * Cdim + h * HD;

        // ---- stage Q through K buffer, load fragments
#pragma unroll
        for (int i2 = 0; i2 < 4; ++i2) {
            const int e = i2 * 128 + tid;
            const int row = e >> 3, ch = e & 7;
            CP_ASYNC16(kb + (uint32_t)(ch * 1024 + row * 16),
                       Q + (size_t)row * Cdim + ch * 8);
        }
        CP_COMMIT(); CP_WAIT(0);
        __syncthreads();

        uint32_t qf[4][4];
        {
            const int qrow = wid * 16 + (lane & 15);
#pragma unroll
            for (int ks = 0; ks < 4; ++ks)
                ldsm_x4(qf[ks], kb + (uint32_t)((2 * ks + (lane >> 4)) * 1024 + qrow * 16));
        }
        __syncthreads();

        float oacc[8][4];
#pragma unroll
        for (int j = 0; j < 8; ++j)
#pragma unroll
            for (int c = 0; c < 4; ++c) oacc[j][c] = 0.f;
        float m0 = -1e30f, m1 = -1e30f, l0 = 0.f, l1 = 0.f;

        load_k(0);

        for (int it = 0; it < nt; ++it) {
            const int k0 = it * 64;

            CP_WAIT(0);                      // K_it resident
            if (tid < 64)
                maskadd[tid] = mrow[k0 + tid] ? -1e30f : 0.f;
            __syncthreads();
            load_v(k0);                      // V_it loads under S compute

            float sacc[8][4];
#pragma unroll
            for (int j = 0; j < 8; ++j)
#pragma unroll
                for (int c = 0; c < 4; ++c) sacc[j][c] = 0.f;

#pragma unroll
            for (int ks = 0; ks < 4; ++ks) {
                uint32_t kf[8][2];
#pragma unroll
                for (int grp = 0; grp < 4; ++grp) {
                    const uint32_t a = (uint32_t)((2 * ks + (lane >> 4)) * 1024 +
                                                  (grp * 16 + (lane & 15)) * 16);
                    uint32_t r[4];
                    ldsm_x4(r, kb + a);
                    kf[2*grp][0] = r[0]; kf[2*grp][1] = r[2];
                    kf[2*grp+1][0] = r[1]; kf[2*grp+1][1] = r[3];
                }
#pragma unroll
                for (int j = 0; j < 8; ++j)
                    mma_f16(sacc[j], qf[ks], kf[j]);
            }

            const bool diag = (k0 == q0);
            float mx0 = -1e30f, mx1 = -1e30f;
#pragma unroll
            for (int j = 0; j < 8; ++j) {
                const float2 ma = *(const float2*)&maskadd[8 * j + 2 * t];
                float s0 = sacc[j][0] + ma.x;
                float s1 = sacc[j][1] + ma.y;
                float s2 = sacc[j][2] + ma.x;
                float s3 = sacc[j][3] + ma.y;
                if (diag) {
                    const int key = k0 + 8 * j + 2 * t;
                    if (key     > qg)     s0 = -1e30f;
                    if (key + 1 > qg)     s1 = -1e30f;
                    if (key     > qg + 8) s2 = -1e30f;
                    if (key + 1 > qg + 8) s3 = -1e30f;
                }
                sacc[j][0] = s0; sacc[j][1] = s1; sacc[j][2] = s2; sacc[j][3] = s3;
                mx0 = fmaxf(mx0, fmaxf(s0, s1));
                mx1 = fmaxf(mx1, fmaxf(s2, s3));
            }
            mx0 = fmaxf(mx0, __shfl_xor_sync(0xFFFFFFFFu, mx0, 1));
            mx0 = fmaxf(mx0, __shfl_xor_sync(0xFFFFFFFFu, mx0, 2));
            mx1 = fmaxf(mx1, __shfl_xor_sync(0xFFFFFFFFu, mx1, 1));
            mx1 = fmaxf(mx1, __shfl_xor_sync(0xFFFFFFFFu, mx1, 2));
            const float mn0 = fmaxf(m0, mx0), mn1 = fmaxf(m1, mx1);
            const float cr0 = fast_exp(m0 - mn0), cr1 = fast_exp(m1 - mn1);
            m0 = mn0; m1 = mn1;
            l0 *= cr0; l1 *= cr1;
#pragma unroll
            for (int j = 0; j < 8; ++j) {
                oacc[j][0] *= cr0; oacc[j][1] *= cr0;
                oacc[j][2] *= cr1; oacc[j][3] *= cr1;
            }

            float sum0 = 0.f, sum1 = 0.f;
            uint32_t pf[4][4];
#pragma unroll
            for (int j = 0; j < 8; ++j) {
                const float p0 = fast_exp(sacc[j][0] - mn0);
                const float p1 = fast_exp(sacc[j][1] - mn0);
                const float p2 = fast_exp(sacc[j][2] - mn1);
                const float p3 = fast_exp(sacc[j][3] - mn1);
                sum0 += p0 + p1; sum1 += p2 + p3;
                const int kk = j >> 1, sl = (j & 1) * 2;
                pf[kk][sl + 0] = pack_f16x2(p0, p1);
                pf[kk][sl + 1] = pack_f16x2(p2, p3);
            }
            sum0 += __shfl_xor_sync(0xFFFFFFFFu, sum0, 1);
            sum0 += __shfl_xor_sync(0xFFFFFFFFu, sum0, 2);
            sum1 += __shfl_xor_sync(0xFFFFFFFFu, sum1, 1);
            sum1 += __shfl_xor_sync(0xFFFFFFFFu, sum1, 2);
            l0 += sum0; l1 += sum1;

            CP_WAIT(0);                      // V_it resident
            __syncthreads();
            if (it + 1 < nt) load_k(k0 + 64);

#pragma unroll
            for (int kp = 0; kp < 4; ++kp) {
                uint32_t vf[8][2];
#pragma unroll
                for (int db = 0; db < 4; ++db) {
                    const uint32_t a = (uint32_t)((2 * db + (lane >> 4)) * 1024 +
                                                  (kp * 16 + (lane & 15)) * 16);
                    uint32_t r[4];
                    ldsm_x4t(r, vb + a);
                    vf[2*db][0] = r[0]; vf[2*db][1] = r[1];
                    vf[2*db+1][0] = r[2]; vf[2*db+1][1] = r[3];
                }
#pragma unroll
                for (int j = 0; j < 8; ++j)
                    mma_f16(oacc[j], pf[kp], vf[j]);
            }
        }

        const float inv0 = 1.f / l0;
        const float inv1 = 1.f / l1;
        __half* o0p = g_at + (mb0 + qg) * Cdim + h * HD;
        __half* o1p = o0p + 8 * Cdim;
#pragma unroll
        for (int j = 0; j < 8; ++j) {
            const int d = 8 * j + 2 * t;
            *(uint32_t*)(o0p + d) = pack_f16x2(oacc[j][0] * inv0, oacc[j][1] * inv0);
            *(uint32_t*)(o1p + d) = pack_f16x2(oacc[j][2] * inv1, oacc[j][3] * inv1);
        }
        __syncthreads();   // buffer reuse safety across sub iterations
    }
}

// ---------------------------------------------------------------------------
extern "C" void kernel_launch(void* const* d_in, const int* in_sizes, int n_in,
                              void* d_out, int out_size)
{
    const float* x     = (const float*)d_in[0];
    const float* y     = (const float*)d_in[1];
    const unsigned char* mask = (const unsigned char*)d_in[2];
    const float* Wq_b  = (const float*)d_in[4];
    const float* Wkv_b = (const float*)d_in[6];
    const float* Wo_b  = (const float*)d_in[8];
    float* out = (float*)d_out;

    convert_all<<<NTOT8 / 256, 256>>>((const float4*)x, (const float4*)y,
                                      (const float4*)d_in[3], (const float4*)d_in[5],
                                      (const float4*)d_in[7]);
    gemm_qkv<<<dim3(8, 64, 3), 256>>>(Wq_b, Wkv_b);
    attn_tc<<<dim3(Sdim / 128, NH, Bdim), 128>>>(mask);
    gemm_o<<<dim3(4, 64), 256>>>(Wo_b, out);
}

// round 15
// speedup vs baseline: 1.0974x; 1.0011x over previous
#include <cuda_runtime.h>
#include <cuda_fp16.h>
#include <cstdint>

// Problem constants
#define Bdim 4
#define Sdim 2048
#define Cdim 1024
#define NH   16
#define HD   64
#define Mrows (Bdim * Sdim)   // 8192

// ---------------------------------------------------------------------------
// Scratch (__device__ globals; referenced ONLY from device code)
// Q/K/V/att stored GEMM-natural: [m][c] with m = b*S+s, c = h*64+d.
// ---------------------------------------------------------------------------
__device__ __align__(16) __half g_q[Mrows * Cdim];
__device__ __align__(16) __half g_k[Mrows * Cdim];
__device__ __align__(16) __half g_v[Mrows * Cdim];

__device__ __align__(16) __half g_x[Mrows * Cdim];
__device__ __align__(16) __half g_y[Mrows * Cdim];
__device__ __align__(16) __half g_at[Mrows * Cdim];
__device__ __align__(16) __half g_wq[Cdim * Cdim];
__device__ __align__(16) __half g_wkv[2 * Cdim * Cdim];
__device__ __align__(16) __half g_wo[Cdim * Cdim];

// ---------------------------------------------------------------------------
// PTX helpers (base sm_103 ISA: cp.async, ldmatrix, mma.sync)
// ---------------------------------------------------------------------------
__device__ __forceinline__ uint32_t smem_u32(const void* p) {
    uint32_t a;
    asm("{ .reg .u64 t; cvta.to.shared.u64 t, %1; cvt.u32.u64 %0, t; }"
        : "=r"(a) : "l"(p));
    return a;
}

#define CP_ASYNC16(sa, ga) \
    asm volatile("cp.async.cg.shared.global [%0], [%1], 16;" :: "r"(sa), "l"(ga) : "memory")
#define CP_COMMIT() asm volatile("cp.async.commit_group;" ::: "memory")
#define CP_WAIT(n)  asm volatile("cp.async.wait_group %0;" :: "n"(n) : "memory")

__device__ __forceinline__ void ldsm_x4(uint32_t* r, uint32_t addr) {
    asm volatile("ldmatrix.sync.aligned.m8n8.x4.shared.b16 {%0,%1,%2,%3}, [%4];"
                 : "=r"(r[0]), "=r"(r[1]), "=r"(r[2]), "=r"(r[3]) : "r"(addr));
}
__device__ __forceinline__ void ldsm_x4t(uint32_t* r, uint32_t addr) {
    asm volatile("ldmatrix.sync.aligned.m8n8.x4.trans.shared.b16 {%0,%1,%2,%3}, [%4];"
                 : "=r"(r[0]), "=r"(r[1]), "=r"(r[2]), "=r"(r[3]) : "r"(addr));
}
__device__ __forceinline__ void mma_f16(float* d, const uint32_t* a, const uint32_t* b) {
    asm volatile("mma.sync.aligned.m16n8k16.row.col.f32.f16.f16.f32 "
                 "{%0,%1,%2,%3}, {%4,%5,%6,%7}, {%8,%9}, {%0,%1,%2,%3};"
                 : "+f"(d[0]), "+f"(d[1]), "+f"(d[2]), "+f"(d[3])
                 : "r"(a[0]), "r"(a[1]), "r"(a[2]), "r"(a[3]), "r"(b[0]), "r"(b[1]));
}

// pack two fp32 -> f16x2 (v0 in low half, v1 in high half)
__device__ __forceinline__ uint32_t pack_f16x2(float v0, float v1) {
    uint32_t r;
    asm("cvt.rn.f16x2.f32 %0, %1, %2;" : "=r"(r) : "f"(v1), "f"(v0));
    return r;
}

// polynomial exp (no MUFU) — valid for x <= ~0, clamped below -80
__device__ __forceinline__ float fast_exp(float x) {
    x = fmaxf(x, -80.f);
    const float y = x * 1.4426950408889634f;
    const float tt = y + 12582912.f;
    const int   i  = __float_as_int(tt);
    const float n  = tt - 12582912.f;
    const float f  = y - n;
    float p = 0.001333355815f;
    p = fmaf(p, f, 0.009618129842f);
    p = fmaf(p, f, 0.05550410866f);
    p = fmaf(p, f, 0.2402265069f);
    p = fmaf(p, f, 0.69314718056f);
    p = fmaf(p, f, 1.0f);
    return __int_as_float(__float_as_int(p) + (i << 23));
}

// ---------------------------------------------------------------------------
// Single fused fp32 -> fp16 convert, 16 elements per thread:
// 4 independent LDG.128 (MLP=4), 2 STG.128.
// ---------------------------------------------------------------------------
#define NX16  (Mrows * Cdim / 16)      // 524288
#define NW16  (Cdim * Cdim / 16)       //  65536
#define NKV16 (2 * Cdim * Cdim / 16)   // 131072
#define NTOT16 (2 * NX16 + 2 * NW16 + NKV16)

__global__ __launch_bounds__(256)
void convert_all(const float4* __restrict__ x, const float4* __restrict__ y,
                 const float4* __restrict__ wq, const float4* __restrict__ wkv,
                 const float4* __restrict__ wo)
{
    const int i = blockIdx.x * 256 + threadIdx.x;
    const float4* src;
    __half* dst;
    int si;
    if (i < NX16)                         { src = x;   dst = g_x;   si = i; }
    else if (i < 2 * NX16)                { src = y;   dst = g_y;   si = i - NX16; }
    else if (i < 2 * NX16 + NW16)         { src = wq;  dst = g_wq;  si = i - 2 * NX16; }
    else if (i < 2 * NX16 + NW16 + NKV16) { src = wkv; dst = g_wkv; si = i - 2 * NX16 - NW16; }
    else                                  { src = wo;  dst = g_wo;  si = i - 2 * NX16 - NW16 - NKV16; }
    const float4 v0 = src[4 * si + 0];
    const float4 v1 = src[4 * si + 1];
    const float4 v2 = src[4 * si + 2];
    const float4 v3 = src[4 * si + 3];
    uint4 o0, o1;
    o0.x = pack_f16x2(v0.x, v0.y);
    o0.y = pack_f16x2(v0.z, v0.w);
    o0.z = pack_f16x2(v1.x, v1.y);
    o0.w = pack_f16x2(v1.z, v1.w);
    o1.x = pack_f16x2(v2.x, v2.y);
    o1.y = pack_f16x2(v2.z, v2.w);
    o1.z = pack_f16x2(v3.x, v3.y);
    o1.w = pack_f16x2(v3.z, v3.w);
    ((uint4*)dst)[2 * si + 0] = o0;
    ((uint4*)dst)[2 * si + 1] = o1;
}

// ---------------------------------------------------------------------------
// gemm_qkv: CTA tile 128x128 (2 CTAs/SM), K stage 32, 2-stage cp.async,
// 32KB static smem. 8 warps 2(M)x4(N), warp tile 64x32.
// grid (8, 64, 3): z=0 Q (scaled 0.125) -> g_q; z=1 K -> g_k; z=2 V -> g_v.
// ---------------------------------------------------------------------------
#define QKV_STAGE 16384u     // A 8KB + B 8KB
#define NSTAGE    32         // K = 1024 / 32

__global__ __launch_bounds__(256)
void gemm_qkv(const float* __restrict__ Wq_b, const float* __restrict__ Wkv_b)
{
    const int z = blockIdx.z;
    const __half* A = (z == 0) ? g_x : g_y;
    const __half* B = (z == 0) ? g_wq : g_wkv;
    const float* bias = (z == 0) ? Wq_b : Wkv_b;
    __half* dst = (z == 0) ? g_q : (z == 1) ? g_k : g_v;
    const int csub = (z == 2) ? 1024 : 0;

    __shared__ __align__(128) char smraw[2 * QKV_STAGE];   // 32 KB static
    const uint32_t smb = smem_u32(smraw);

    const int tid = threadIdx.x;
    const int wid = tid >> 5;
    const int lane = tid & 31;
    const int m0 = blockIdx.y * 128;
    const int n0 = ((z == 2) ? 1024 : 0) + blockIdx.x * 128;
    const int warp_m = (wid & 1) * 64;
    const int warp_n = (wid >> 1) * 32;

    float acc[4][4][4];
#pragma unroll
    for (int i = 0; i < 4; ++i)
#pragma unroll
        for (int j = 0; j < 4; ++j)
#pragma unroll
            for (int c = 0; c < 4; ++c) acc[i][j][c] = 0.f;

    auto load_stage = [&](int s) {
        const int k0g = s * 32;
        const uint32_t bufb = smb + (uint32_t)(s & 1) * QKV_STAGE;
#pragma unroll
        for (int i = 0; i < 2; ++i) {
            const int e = i * 256 + tid;          // 0..511
            const int row = e >> 2, ch = e & 3;
            CP_ASYNC16(bufb + (uint32_t)(ch * 2048 + row * 16),
                       A + (size_t)(m0 + row) * Cdim + k0g + ch * 8);
        }
#pragma unroll
        for (int i = 0; i < 2; ++i) {
            const int e = i * 256 + tid;
            const int row = e >> 2, ch = e & 3;
            CP_ASYNC16(bufb + 8192u + (uint32_t)(ch * 2048 + row * 16),
                       B + (size_t)(n0 + row) * Cdim + k0g + ch * 8);
        }
        CP_COMMIT();
    };

    load_stage(0);

    for (int s = 0; s < NSTAGE; ++s) {
        CP_WAIT(0);
        __syncthreads();
        if (s + 1 < NSTAGE) load_stage(s + 1);

        const uint32_t bufb = smb + (uint32_t)(s & 1) * QKV_STAGE;
        const uint32_t bA = bufb;
        const uint32_t bB = bufb + 8192u;

#pragma unroll
        for (int k16 = 0; k16 < 2; ++k16) {
            uint32_t af[4][4];
            {
                const int arow = warp_m + (lane & 15);
                const int kc = k16 * 2 + (lane >> 4);
#pragma unroll
                for (int tm = 0; tm < 4; ++tm)
                    ldsm_x4(af[tm], bA + (uint32_t)(kc * 2048 + (arow + tm * 16) * 16));
            }
            uint32_t bf[4][2];
            {
                const int gg = lane >> 3;
                const int nr = (lane & 7) + ((gg >> 1) << 3);
                const int kc = k16 * 2 + (gg & 1);
#pragma unroll
                for (int half = 0; half < 2; ++half) {
                    const int row = warp_n + half * 16 + nr;
                    uint32_t r4[4];
                    ldsm_x4(r4, bB + (uint32_t)(kc * 2048 + row * 16));
                    bf[half * 2 + 0][0] = r4[0]; bf[half * 2 + 0][1] = r4[1];
                    bf[half * 2 + 1][0] = r4[2]; bf[half * 2 + 1][1] = r4[3];
                }
            }
#pragma unroll
            for (int tm = 0; tm < 4; ++tm)
#pragma unroll
                for (int tn = 0; tn < 4; ++tn)
                    mma_f16(acc[tm][tn], af[tm], bf[tn]);
        }
        __syncthreads();
    }

    const float qscale = (z == 0) ? 0.125f : 1.0f;
#pragma unroll
    for (int tm = 0; tm < 4; ++tm) {
#pragma unroll
        for (int tn = 0; tn < 4; ++tn) {
            const int rbase = m0 + warp_m + tm * 16 + (lane >> 2);
            const int c = n0 + warp_n + tn * 8 + (lane & 3) * 2;
            const float b0 = bias[c], b1 = bias[c + 1];
            const int cc = c - csub;
#pragma unroll
            for (int half = 0; half < 2; ++half) {
                const int m = rbase + half * 8;
                const float v0 = (acc[tm][tn][half * 2 + 0] + b0) * qscale;
                const float v1 = (acc[tm][tn][half * 2 + 1] + b1) * qscale;
                *(uint32_t*)(dst + (size_t)m * Cdim + cc) = pack_f16x2(v0, v1);
            }
        }
    }
}

// ---------------------------------------------------------------------------
// gemm_o: CTA tile 128x256, K stage 32, 2-stage cp.async, 48KB static smem.
// 8 warps 2(M)x4(N), warp tile 64x64. out = g_at @ Wo^T + b. grid (4, 64).
// ---------------------------------------------------------------------------
#define A_TILE  8192u
#define STAGE_B 24576u

__global__ __launch_bounds__(256)
void gemm_o(const float* __restrict__ Wo_b, float* __restrict__ out)
{
    __shared__ __align__(128) char smraw[2 * STAGE_B];
    const uint32_t smb = smem_u32(smraw);

    const int tid = threadIdx.x;
    const int wid = tid >> 5;
    const int lane = tid & 31;
    const int m0 = blockIdx.y * 128;
    const int n0 = blockIdx.x * 256;
    const int warp_m = (wid & 1) * 64;
    const int warp_n = (wid >> 1) * 64;

    float acc[4][8][4];
#pragma unroll
    for (int i = 0; i < 4; ++i)
#pragma unroll
        for (int j = 0; j < 8; ++j)
#pragma unroll
            for (int c = 0; c < 4; ++c) acc[i][j][c] = 0.f;

    auto load_stage = [&](int s) {
        const int k0g = s * 32;
        const uint32_t bufb = smb + (uint32_t)(s & 1) * STAGE_B;
#pragma unroll
        for (int i = 0; i < 2; ++i) {
            const int e = i * 256 + tid;
            const int row = e >> 2, ch = e & 3;
            CP_ASYNC16(bufb + (uint32_t)(ch * 2048 + row * 16),
                       g_at + (size_t)(m0 + row) * Cdim + k0g + ch * 8);
        }
#pragma unroll
        for (int i = 0; i < 4; ++i) {
            const int e = i * 256 + tid;
            const int row = e >> 2, ch = e & 3;
            CP_ASYNC16(bufb + A_TILE + (uint32_t)(ch * 4096 + row * 16),
                       g_wo + (size_t)(n0 + row) * Cdim + k0g + ch * 8);
        }
        CP_COMMIT();
    };

    load_stage(0);

    for (int s = 0; s < NSTAGE; ++s) {
        CP_WAIT(0);
        __syncthreads();
        if (s + 1 < NSTAGE) load_stage(s + 1);

        const uint32_t bufb = smb + (uint32_t)(s & 1) * STAGE_B;
        const uint32_t bA = bufb;
        const uint32_t bB = bufb + A_TILE;

#pragma unroll
        for (int k16 = 0; k16 < 2; ++k16) {
            uint32_t af[4][4];
            {
                const int arow = warp_m + (lane & 15);
                const int kc = k16 * 2 + (lane >> 4);
#pragma unroll
                for (int tm = 0; tm < 4; ++tm)
                    ldsm_x4(af[tm], bA + (uint32_t)(kc * 2048 + (arow + tm * 16) * 16));
            }
            uint32_t bf[8][2];
            {
                const int gg = lane >> 3;
                const int nr = (lane & 7) + ((gg >> 1) << 3);
                const int kc = k16 * 2 + (gg & 1);
#pragma unroll
                for (int half = 0; half < 4; ++half) {
                    const int row = warp_n + half * 16 + nr;
                    uint32_t r4[4];
                    ldsm_x4(r4, bB + (uint32_t)(kc * 4096 + row * 16));
                    bf[half * 2 + 0][0] = r4[0]; bf[half * 2 + 0][1] = r4[1];
                    bf[half * 2 + 1][0] = r4[2]; bf[half * 2 + 1][1] = r4[3];
                }
            }
#pragma unroll
            for (int tm = 0; tm < 4; ++tm)
#pragma unroll
                for (int tn = 0; tn < 8; ++tn)
                    mma_f16(acc[tm][tn], af[tm], bf[tn]);
        }
        __syncthreads();
    }

#pragma unroll
    for (int tm = 0; tm < 4; ++tm) {
#pragma unroll
        for (int tn = 0; tn < 8; ++tn) {
            const int rbase = m0 + warp_m + tm * 16 + (lane >> 2);
            const int c = n0 + warp_n + tn * 8 + (lane & 3) * 2;
            const float b0 = Wo_b[c], b1 = Wo_b[c + 1];
#pragma unroll
            for (int half = 0; half < 2; ++half) {
                const int m = rbase + half * 8;
                float2 o;
                o.x = acc[tm][tn][half * 2 + 0] + b0;
                o.y = acc[tm][tn][half * 2 + 1] + b1;
                *(float2*)(out + (size_t)m * Cdim + c) = o;
            }
        }
    }
}

// ---------------------------------------------------------------------------
// Tensor-core fp16 flash attention (2 buffers, staggered K/V, maskadd smem,
// triangle pairing). Q/K/V in [m][h*64+d] layout.
// grid (16, NH, B); CTA does q-block bx AND q-block (31-bx): 33 tiles each.
// ---------------------------------------------------------------------------
__global__ __launch_bounds__(128)
void attn_tc(const unsigned char* __restrict__ mask)
{
    __shared__ __align__(128) unsigned char kvraw[16384];
    __shared__ __align__(8) float maskadd[64];

    const int h  = blockIdx.y;
    const int b  = blockIdx.z;
    const int tid = threadIdx.x;
    const int wid = tid >> 5;
    const int lane = tid & 31;
    const int g = lane >> 2, t = lane & 3;

    const uint32_t smb = smem_u32(kvraw);
    const uint32_t kb = smb;
    const uint32_t vb = smb + 8192;

    const size_t mb0 = (size_t)b * Sdim;
    const __half* K = g_k + mb0 * Cdim + h * HD;
    const __half* V = g_v + mb0 * Cdim + h * HD;
    const unsigned char* mrow = mask + mb0;

    auto load_k = [&](int k0) {
#pragma unroll
        for (int i2 = 0; i2 < 4; ++i2) {
            const int e = i2 * 128 + tid;
            const int row = e >> 3, ch = e & 7;
            CP_ASYNC16(kb + (uint32_t)(ch * 1024 + row * 16),
                       K + (size_t)(k0 + row) * Cdim + ch * 8);
        }
        CP_COMMIT();
    };
    auto load_v = [&](int k0) {
#pragma unroll
        for (int i2 = 0; i2 < 4; ++i2) {
            const int e = i2 * 128 + tid;
            const int row = e >> 3, ch = e & 7;
            CP_ASYNC16(vb + (uint32_t)(ch * 1024 + row * 16),
                       V + (size_t)(k0 + row) * Cdim + ch * 8);
        }
        CP_COMMIT();
    };

#pragma unroll 1
    for (int sub = 0; sub < 2; ++sub) {
        const int qblk = (sub == 0) ? (int)blockIdx.x
                                    : (Sdim / 64 - 1 - (int)blockIdx.x);
        const int q0 = qblk * 64;
        const int nt = qblk + 1;
        const int qg = q0 + wid * 16 + g;
        const __half* Q = g_q + (mb0 + q0) * Cdim + h * HD;

        // ---- stage Q through K buffer, load fragments
#pragma unroll
        for (int i2 = 0; i2 < 4; ++i2) {
            const int e = i2 * 128 + tid;
            const int row = e >> 3, ch = e & 7;
            CP_ASYNC16(kb + (uint32_t)(ch * 1024 + row * 16),
                       Q + (size_t)row * Cdim + ch * 8);
        }
        CP_COMMIT(); CP_WAIT(0);
        __syncthreads();

        uint32_t qf[4][4];
        {
            const int qrow = wid * 16 + (lane & 15);
#pragma unroll
            for (int ks = 0; ks < 4; ++ks)
                ldsm_x4(qf[ks], kb + (uint32_t)((2 * ks + (lane >> 4)) * 1024 + qrow * 16));
        }
        __syncthreads();

        float oacc[8][4];
#pragma unroll
        for (int j = 0; j < 8; ++j)
#pragma unroll
            for (int c = 0; c < 4; ++c) oacc[j][c] = 0.f;
        float m0 = -1e30f, m1 = -1e30f, l0 = 0.f, l1 = 0.f;

        load_k(0);

        for (int it = 0; it < nt; ++it) {
            const int k0 = it * 64;

            CP_WAIT(0);                      // K_it resident
            if (tid < 64)
                maskadd[tid] = mrow[k0 + tid] ? -1e30f : 0.f;
            __syncthreads();
            load_v(k0);                      // V_it loads under S compute

            float sacc[8][4];
#pragma unroll
            for (int j = 0; j < 8; ++j)
#pragma unroll
                for (int c = 0; c < 4; ++c) sacc[j][c] = 0.f;

#pragma unroll
            for (int ks = 0; ks < 4; ++ks) {
                uint32_t kf[8][2];
#pragma unroll
                for (int grp = 0; grp < 4; ++grp) {
                    const uint32_t a = (uint32_t)((2 * ks + (lane >> 4)) * 1024 +
                                                  (grp * 16 + (lane & 15)) * 16);
                    uint32_t r[4];
                    ldsm_x4(r, kb + a);
                    kf[2*grp][0] = r[0]; kf[2*grp][1] = r[2];
                    kf[2*grp+1][0] = r[1]; kf[2*grp+1][1] = r[3];
                }
#pragma unroll
                for (int j = 0; j < 8; ++j)
                    mma_f16(sacc[j], qf[ks], kf[j]);
            }

            const bool diag = (k0 == q0);
            float mx0 = -1e30f, mx1 = -1e30f;
#pragma unroll
            for (int j = 0; j < 8; ++j) {
                const float2 ma = *(const float2*)&maskadd[8 * j + 2 * t];
                float s0 = sacc[j][0] + ma.x;
                float s1 = sacc[j][1] + ma.y;
                float s2 = sacc[j][2] + ma.x;
                float s3 = sacc[j][3] + ma.y;
                if (diag) {
                    const int key = k0 + 8 * j + 2 * t;
                    if (key     > qg)     s0 = -1e30f;
                    if (key + 1 > qg)     s1 = -1e30f;
                    if (key     > qg + 8) s2 = -1e30f;
                    if (key + 1 > qg + 8) s3 = -1e30f;
                }
                sacc[j][0] = s0; sacc[j][1] = s1; sacc[j][2] = s2; sacc[j][3] = s3;
                mx0 = fmaxf(mx0, fmaxf(s0, s1));
                mx1 = fmaxf(mx1, fmaxf(s2, s3));
            }
            mx0 = fmaxf(mx0, __shfl_xor_sync(0xFFFFFFFFu, mx0, 1));
            mx0 = fmaxf(mx0, __shfl_xor_sync(0xFFFFFFFFu, mx0, 2));
            mx1 = fmaxf(mx1, __shfl_xor_sync(0xFFFFFFFFu, mx1, 1));
            mx1 = fmaxf(mx1, __shfl_xor_sync(0xFFFFFFFFu, mx1, 2));
            const float mn0 = fmaxf(m0, mx0), mn1 = fmaxf(m1, mx1);
            const float cr0 = fast_exp(m0 - mn0), cr1 = fast_exp(m1 - mn1);
            m0 = mn0; m1 = mn1;
            l0 *= cr0; l1 *= cr1;
#pragma unroll
            for (int j = 0; j < 8; ++j) {
                oacc[j][0] *= cr0; oacc[j][1] *= cr0;
                oacc[j][2] *= cr1; oacc[j][3] *= cr1;
            }

            float sum0 = 0.f, sum1 = 0.f;
            uint32_t pf[4][4];
#pragma unroll
            for (int j = 0; j < 8; ++j) {
                const float p0 = fast_exp(sacc[j][0] - mn0);
                const float p1 = fast_exp(sacc[j][1] - mn0);
                const float p2 = fast_exp(sacc[j][2] - mn1);
                const float p3 = fast_exp(sacc[j][3] - mn1);
                sum0 += p0 + p1; sum1 += p2 + p3;
                const int kk = j >> 1, sl = (j & 1) * 2;
                pf[kk][sl + 0] = pack_f16x2(p0, p1);
                pf[kk][sl + 1] = pack_f16x2(p2, p3);
            }
            sum0 += __shfl_xor_sync(0xFFFFFFFFu, sum0, 1);
            sum0 += __shfl_xor_sync(0xFFFFFFFFu, sum0, 2);
            sum1 += __shfl_xor_sync(0xFFFFFFFFu, sum1, 1);
            sum1 += __shfl_xor_sync(0xFFFFFFFFu, sum1, 2);
            l0 += sum0; l1 += sum1;

            CP_WAIT(0);                      // V_it resident
            __syncthreads();
            if (it + 1 < nt) load_k(k0 + 64);

#pragma unroll
            for (int kp = 0; kp < 4; ++kp) {
                uint32_t vf[8][2];
#pragma unroll
                for (int db = 0; db < 4; ++db) {
                    const uint32_t a = (uint32_t)((2 * db + (lane >> 4)) * 1024 +
                                                  (kp * 16 + (lane & 15)) * 16);
                    uint32_t r[4];
                    ldsm_x4t(r, vb + a);
                    vf[2*db][0] = r[0]; vf[2*db][1] = r[1];
                    vf[2*db+1][0] = r[2]; vf[2*db+1][1] = r[3];
                }
#pragma unroll
                for (int j = 0; j < 8; ++j)
                    mma_f16(oacc[j], pf[kp], vf[j]);
            }
        }

        const float inv0 = 1.f / l0;
        const float inv1 = 1.f / l1;
        __half* o0p = g_at + (mb0 + qg) * Cdim + h * HD;
        __half* o1p = o0p + 8 * Cdim;
#pragma unroll
        for (int j = 0; j < 8; ++j) {
            const int d = 8 * j + 2 * t;
            *(uint32_t*)(o0p + d) = pack_f16x2(oacc[j][0] * inv0, oacc[j][1] * inv0);
            *(uint32_t*)(o1p + d) = pack_f16x2(oacc[j][2] * inv1, oacc[j][3] * inv1);
        }
        __syncthreads();   // buffer reuse safety across sub iterations
    }
}

// ---------------------------------------------------------------------------
extern "C" void kernel_launch(void* const* d_in, const int* in_sizes, int n_in,
                              void* d_out, int out_size)
{
    const float* x     = (const float*)d_in[0];
    const float* y     = (const float*)d_in[1];
    const unsigned char* mask = (const unsigned char*)d_in[2];
    const float* Wq_b  = (const float*)d_in[4];
    const float* Wkv_b = (const float*)d_in[6];
    const float* Wo_b  = (const float*)d_in[8];
    float* out = (float*)d_out;

    convert_all<<<NTOT16 / 256, 256>>>((const float4*)x, (const float4*)y,
                                       (const float4*)d_in[3], (const float4*)d_in[5],
                                       (const float4*)d_in[7]);
    gemm_qkv<<<dim3(8, 64, 3), 256>>>(Wq_b, Wkv_b);
    attn_tc<<<dim3(Sdim / 128, NH, Bdim), 128>>>(mask);
    gemm_o<<<dim3(4, 64), 256>>>(Wo_b, out);
}

// round 16
// speedup vs baseline: 1.1128x; 1.0140x over previous
#include <cuda_runtime.h>
#include <cuda_fp16.h>
#include <cstdint>

// Problem constants
#define Bdim 4
#define Sdim 2048
#define Cdim 1024
#define NH   16
#define HD   64
#define Mrows (Bdim * Sdim)   // 8192

// ---------------------------------------------------------------------------
// Scratch (__device__ globals; referenced ONLY from device code)
// Q/K/V/att stored GEMM-natural: [m][c] with m = b*S+s, c = h*64+d.
// ---------------------------------------------------------------------------
__device__ __align__(16) __half g_q[Mrows * Cdim];
__device__ __align__(16) __half g_k[Mrows * Cdim];
__device__ __align__(16) __half g_v[Mrows * Cdim];

__device__ __align__(16) __half g_x[Mrows * Cdim];
__device__ __align__(16) __half g_y[Mrows * Cdim];
__device__ __align__(16) __half g_at[Mrows * Cdim];
__device__ __align__(16) __half g_wq[Cdim * Cdim];
__device__ __align__(16) __half g_wkv[2 * Cdim * Cdim];
__device__ __align__(16) __half g_wo[Cdim * Cdim];

// ---------------------------------------------------------------------------
// PTX helpers (base sm_103 ISA: cp.async, ldmatrix, mma.sync)
// ---------------------------------------------------------------------------
__device__ __forceinline__ uint32_t smem_u32(const void* p) {
    uint32_t a;
    asm("{ .reg .u64 t; cvta.to.shared.u64 t, %1; cvt.u32.u64 %0, t; }"
        : "=r"(a) : "l"(p));
    return a;
}

#define CP_ASYNC16(sa, ga) \
    asm volatile("cp.async.cg.shared.global [%0], [%1], 16;" :: "r"(sa), "l"(ga) : "memory")
#define CP_COMMIT() asm volatile("cp.async.commit_group;" ::: "memory")
#define CP_WAIT(n)  asm volatile("cp.async.wait_group %0;" :: "n"(n) : "memory")

__device__ __forceinline__ void ldsm_x4(uint32_t* r, uint32_t addr) {
    asm volatile("ldmatrix.sync.aligned.m8n8.x4.shared.b16 {%0,%1,%2,%3}, [%4];"
                 : "=r"(r[0]), "=r"(r[1]), "=r"(r[2]), "=r"(r[3]) : "r"(addr));
}
__device__ __forceinline__ void ldsm_x4t(uint32_t* r, uint32_t addr) {
    asm volatile("ldmatrix.sync.aligned.m8n8.x4.trans.shared.b16 {%0,%1,%2,%3}, [%4];"
                 : "=r"(r[0]), "=r"(r[1]), "=r"(r[2]), "=r"(r[3]) : "r"(addr));
}
__device__ __forceinline__ void mma_f16(float* d, const uint32_t* a, const uint32_t* b) {
    asm volatile("mma.sync.aligned.m16n8k16.row.col.f32.f16.f16.f32 "
                 "{%0,%1,%2,%3}, {%4,%5,%6,%7}, {%8,%9}, {%0,%1,%2,%3};"
                 : "+f"(d[0]), "+f"(d[1]), "+f"(d[2]), "+f"(d[3])
                 : "r"(a[0]), "r"(a[1]), "r"(a[2]), "r"(a[3]), "r"(b[0]), "r"(b[1]));
}

// pack two fp32 -> f16x2 (v0 in low half, v1 in high half)
__device__ __forceinline__ uint32_t pack_f16x2(float v0, float v1) {
    uint32_t r;
    asm("cvt.rn.f16x2.f32 %0, %1, %2;" : "=r"(r) : "f"(v1), "f"(v0));
    return r;
}

// polynomial exp (no MUFU) — valid for x <= ~0, clamped below -80
__device__ __forceinline__ float fast_exp(float x) {
    x = fmaxf(x, -80.f);
    const float y = x * 1.4426950408889634f;
    const float tt = y + 12582912.f;
    const int   i  = __float_as_int(tt);
    const float n  = tt - 12582912.f;
    const float f  = y - n;
    float p = 0.001333355815f;
    p = fmaf(p, f, 0.009618129842f);
    p = fmaf(p, f, 0.05550410866f);
    p = fmaf(p, f, 0.2402265069f);
    p = fmaf(p, f, 0.69314718056f);
    p = fmaf(p, f, 1.0f);
    return __int_as_float(__float_as_int(p) + (i << 23));
}

// ---------------------------------------------------------------------------
// Single fused fp32 -> fp16 convert, 16 elements per thread.
// ---------------------------------------------------------------------------
#define NX16  (Mrows * Cdim / 16)
#define NW16  (Cdim * Cdim / 16)
#define NKV16 (2 * Cdim * Cdim / 16)
#define NTOT16 (2 * NX16 + 2 * NW16 + NKV16)

__global__ __launch_bounds__(256)
void convert_all(const float4* __restrict__ x, const float4* __restrict__ y,
                 const float4* __restrict__ wq, const float4* __restrict__ wkv,
                 const float4* __restrict__ wo)
{
    const int i = blockIdx.x * 256 + threadIdx.x;
    const float4* src;
    __half* dst;
    int si;
    if (i < NX16)                         { src = x;   dst = g_x;   si = i; }
    else if (i < 2 * NX16)                { src = y;   dst = g_y;   si = i - NX16; }
    else if (i < 2 * NX16 + NW16)         { src = wq;  dst = g_wq;  si = i - 2 * NX16; }
    else if (i < 2 * NX16 + NW16 + NKV16) { src = wkv; dst = g_wkv; si = i - 2 * NX16 - NW16; }
    else                                  { src = wo;  dst = g_wo;  si = i - 2 * NX16 - NW16 - NKV16; }
    const float4 v0 = src[4 * si + 0];
    const float4 v1 = src[4 * si + 1];
    const float4 v2 = src[4 * si + 2];
    const float4 v3 = src[4 * si + 3];
    uint4 o0, o1;
    o0.x = pack_f16x2(v0.x, v0.y);
    o0.y = pack_f16x2(v0.z, v0.w);
    o0.z = pack_f16x2(v1.x, v1.y);
    o0.w = pack_f16x2(v1.z, v1.w);
    o1.x = pack_f16x2(v2.x, v2.y);
    o1.y = pack_f16x2(v2.z, v2.w);
    o1.z = pack_f16x2(v3.x, v3.y);
    o1.w = pack_f16x2(v3.z, v3.w);
    ((uint4*)dst)[2 * si + 0] = o0;
    ((uint4*)dst)[2 * si + 1] = o1;
}

// ---------------------------------------------------------------------------
// gemm_qkv: CTA tile 128x128 (2 CTAs/SM), K stage 32, 2-stage cp.async,
// 32KB static smem. 8 warps 2(M)x4(N), warp tile 64x32.
// grid (8, 64, 3): z=0 Q (scaled 0.125) -> g_q; z=1 K -> g_k; z=2 V -> g_v.
// ---------------------------------------------------------------------------
#define QKV_STAGE 16384u     // A 8KB + B 8KB
#define NSTAGE    32         // K = 1024 / 32

__global__ __launch_bounds__(256)
void gemm_qkv(const float* __restrict__ Wq_b, const float* __restrict__ Wkv_b)
{
    const int z = blockIdx.z;
    const __half* A = (z == 0) ? g_x : g_y;
    const __half* B = (z == 0) ? g_wq : g_wkv;
    const float* bias = (z == 0) ? Wq_b : Wkv_b;
    __half* dst = (z == 0) ? g_q : (z == 1) ? g_k : g_v;
    const int csub = (z == 2) ? 1024 : 0;

    __shared__ __align__(128) char smraw[2 * QKV_STAGE];   // 32 KB static
    const uint32_t smb = smem_u32(smraw);

    const int tid = threadIdx.x;
    const int wid = tid >> 5;
    const int lane = tid & 31;
    const int m0 = blockIdx.y * 128;
    const int n0 = ((z == 2) ? 1024 : 0) + blockIdx.x * 128;
    const int warp_m = (wid & 1) * 64;
    const int warp_n = (wid >> 1) * 32;

    float acc[4][4][4];
#pragma unroll
    for (int i = 0; i < 4; ++i)
#pragma unroll
        for (int j = 0; j < 4; ++j)
#pragma unroll
            for (int c = 0; c < 4; ++c) acc[i][j][c] = 0.f;

    auto load_stage = [&](int s) {
        const int k0g = s * 32;
        const uint32_t bufb = smb + (uint32_t)(s & 1) * QKV_STAGE;
#pragma unroll
        for (int i = 0; i < 2; ++i) {
            const int e = i * 256 + tid;          // 0..511
            const int row = e >> 2, ch = e & 3;
            CP_ASYNC16(bufb + (uint32_t)(ch * 2048 + row * 16),
                       A + (size_t)(m0 + row) * Cdim + k0g + ch * 8);
        }
#pragma unroll
        for (int i = 0; i < 2; ++i) {
            const int e = i * 256 + tid;
            const int row = e >> 2, ch = e & 3;
            CP_ASYNC16(bufb + 8192u + (uint32_t)(ch * 2048 + row * 16),
                       B + (size_t)(n0 + row) * Cdim + k0g + ch * 8);
        }
        CP_COMMIT();
    };

    load_stage(0);

    for (int s = 0; s < NSTAGE; ++s) {
        CP_WAIT(0);
        __syncthreads();
        if (s + 1 < NSTAGE) load_stage(s + 1);

        const uint32_t bufb = smb + (uint32_t)(s & 1) * QKV_STAGE;
        const uint32_t bA = bufb;
        const uint32_t bB = bufb + 8192u;

#pragma unroll
        for (int k16 = 0; k16 < 2; ++k16) {
            uint32_t af[4][4];
            {
                const int arow = warp_m + (lane & 15);
                const int kc = k16 * 2 + (lane >> 4);
#pragma unroll
                for (int tm = 0; tm < 4; ++tm)
                    ldsm_x4(af[tm], bA + (uint32_t)(kc * 2048 + (arow + tm * 16) * 16));
            }
            uint32_t bf[4][2];
            {
                const int gg = lane >> 3;
                const int nr = (lane & 7) + ((gg >> 1) << 3);
                const int kc = k16 * 2 + (gg & 1);
#pragma unroll
                for (int half = 0; half < 2; ++half) {
                    const int row = warp_n + half * 16 + nr;
                    uint32_t r4[4];
                    ldsm_x4(r4, bB + (uint32_t)(kc * 2048 + row * 16));
                    bf[half * 2 + 0][0] = r4[0]; bf[half * 2 + 0][1] = r4[1];
                    bf[half * 2 + 1][0] = r4[2]; bf[half * 2 + 1][1] = r4[3];
                }
            }
#pragma unroll
            for (int tm = 0; tm < 4; ++tm)
#pragma unroll
                for (int tn = 0; tn < 4; ++tn)
                    mma_f16(acc[tm][tn], af[tm], bf[tn]);
        }
        __syncthreads();
    }

    const float qscale = (z == 0) ? 0.125f : 1.0f;
#pragma unroll
    for (int tm = 0; tm < 4; ++tm) {
#pragma unroll
        for (int tn = 0; tn < 4; ++tn) {
            const int rbase = m0 + warp_m + tm * 16 + (lane >> 2);
            const int c = n0 + warp_n + tn * 8 + (lane & 3) * 2;
            const float b0 = bias[c], b1 = bias[c + 1];
            const int cc = c - csub;
#pragma unroll
            for (int half = 0; half < 2; ++half) {
                const int m = rbase + half * 8;
                const float v0 = (acc[tm][tn][half * 2 + 0] + b0) * qscale;
                const float v1 = (acc[tm][tn][half * 2 + 1] + b1) * qscale;
                *(uint32_t*)(dst + (size_t)m * Cdim + cc) = pack_f16x2(v0, v1);
            }
        }
    }
}

// ---------------------------------------------------------------------------
// gemm_o: SAME 128x128 / 2-CTA-per-SM structure as gemm_qkv (measured 20%
// faster per MAC than the 128x256 1-CTA variant); fp32 epilogue.
// out = g_at @ Wo^T + b. grid (8, 64).
// ---------------------------------------------------------------------------
__global__ __launch_bounds__(256)
void gemm_o(const float* __restrict__ Wo_b, float* __restrict__ out)
{
    __shared__ __align__(128) char smraw[2 * QKV_STAGE];   // 32 KB static
    const uint32_t smb = smem_u32(smraw);

    const int tid = threadIdx.x;
    const int wid = tid >> 5;
    const int lane = tid & 31;
    const int m0 = blockIdx.y * 128;
    const int n0 = blockIdx.x * 128;
    const int warp_m = (wid & 1) * 64;
    const int warp_n = (wid >> 1) * 32;

    float acc[4][4][4];
#pragma unroll
    for (int i = 0; i < 4; ++i)
#pragma unroll
        for (int j = 0; j < 4; ++j)
#pragma unroll
            for (int c = 0; c < 4; ++c) acc[i][j][c] = 0.f;

    auto load_stage = [&](int s) {
        const int k0g = s * 32;
        const uint32_t bufb = smb + (uint32_t)(s & 1) * QKV_STAGE;
#pragma unroll
        for (int i = 0; i < 2; ++i) {
            const int e = i * 256 + tid;
            const int row = e >> 2, ch = e & 3;
            CP_ASYNC16(bufb + (uint32_t)(ch * 2048 + row * 16),
                       g_at + (size_t)(m0 + row) * Cdim + k0g + ch * 8);
        }
#pragma unroll
        for (int i = 0; i < 2; ++i) {
            const int e = i * 256 + tid;
            const int row = e >> 2, ch = e & 3;
            CP_ASYNC16(bufb + 8192u + (uint32_t)(ch * 2048 + row * 16),
                       g_wo + (size_t)(n0 + row) * Cdim + k0g + ch * 8);
        }
        CP_COMMIT();
    };

    load_stage(0);

    for (int s = 0; s < NSTAGE; ++s) {
        CP_WAIT(0);
        __syncthreads();
        if (s + 1 < NSTAGE) load_stage(s + 1);

        const uint32_t bufb = smb + (uint32_t)(s & 1) * QKV_STAGE;
        const uint32_t bA = bufb;
        const uint32_t bB = bufb + 8192u;

#pragma unroll
        for (int k16 = 0; k16 < 2; ++k16) {
            uint32_t af[4][4];
            {
                const int arow = warp_m + (lane & 15);
                const int kc = k16 * 2 + (lane >> 4);
#pragma unroll
                for (int tm = 0; tm < 4; ++tm)
                    ldsm_x4(af[tm], bA + (uint32_t)(kc * 2048 + (arow + tm * 16) * 16));
            }
            uint32_t bf[4][2];
            {
                const int gg = lane >> 3;
                const int nr = (lane & 7) + ((gg >> 1) << 3);
                const int kc = k16 * 2 + (gg & 1);
#pragma unroll
                for (int half = 0; half < 2; ++half) {
                    const int row = warp_n + half * 16 + nr;
                    uint32_t r4[4];
                    ldsm_x4(r4, bB + (uint32_t)(kc * 2048 + row * 16));
                    bf[half * 2 + 0][0] = r4[0]; bf[half * 2 + 0][1] = r4[1];
                    bf[half * 2 + 1][0] = r4[2]; bf[half * 2 + 1][1] = r4[3];
                }
            }
#pragma unroll
            for (int tm = 0; tm < 4; ++tm)
#pragma unroll
                for (int tn = 0; tn < 4; ++tn)
                    mma_f16(acc[tm][tn], af[tm], bf[tn]);
        }
        __syncthreads();
    }

#pragma unroll
    for (int tm = 0; tm < 4; ++tm) {
#pragma unroll
        for (int tn = 0; tn < 4; ++tn) {
            const int rbase = m0 + warp_m + tm * 16 + (lane >> 2);
            const int c = n0 + warp_n + tn * 8 + (lane & 3) * 2;
            const float b0 = Wo_b[c], b1 = Wo_b[c + 1];
#pragma unroll
            for (int half = 0; half < 2; ++half) {
                const int m = rbase + half * 8;
                float2 o;
                o.x = acc[tm][tn][half * 2 + 0] + b0;
                o.y = acc[tm][tn][half * 2 + 1] + b1;
                *(float2*)(out + (size_t)m * Cdim + c) = o;
            }
        }
    }
}

// ---------------------------------------------------------------------------
// Tensor-core fp16 flash attention (2 buffers, staggered K/V, maskadd smem,
// triangle pairing). Q/K/V in [m][h*64+d] layout.
// grid (16, NH, B); CTA does q-block bx AND q-block (31-bx): 33 tiles each.
// ---------------------------------------------------------------------------
__global__ __launch_bounds__(128)
void attn_tc(const unsigned char* __restrict__ mask)
{
    __shared__ __align__(128) unsigned char kvraw[16384];
    __shared__ __align__(8) float maskadd[64];

    const int h  = blockIdx.y;
    const int b  = blockIdx.z;
    const int tid = threadIdx.x;
    const int wid = tid >> 5;
    const int lane = tid & 31;
    const int g = lane >> 2, t = lane & 3;

    const uint32_t smb = smem_u32(kvraw);
    const uint32_t kb = smb;
    const uint32_t vb = smb + 8192;

    const size_t mb0 = (size_t)b * Sdim;
    const __half* K = g_k + mb0 * Cdim + h * HD;
    const __half* V = g_v + mb0 * Cdim + h * HD;
    const unsigned char* mrow = mask + mb0;

    auto load_k = [&](int k0) {
#pragma unroll
        for (int i2 = 0; i2 < 4; ++i2) {
            const int e = i2 * 128 + tid;
            const int row = e >> 3, ch = e & 7;
            CP_ASYNC16(kb + (uint32_t)(ch * 1024 + row * 16),
                       K + (size_t)(k0 + row) * Cdim + ch * 8);
        }
        CP_COMMIT();
    };
    auto load_v = [&](int k0) {
#pragma unroll
        for (int i2 = 0; i2 < 4; ++i2) {
            const int e = i2 * 128 + tid;
            const int row = e >> 3, ch = e & 7;
            CP_ASYNC16(vb + (uint32_t)(ch * 1024 + row * 16),
                       V + (size_t)(k0 + row) * Cdim + ch * 8);
        }
        CP_COMMIT();
    };

#pragma unroll 1
    for (int sub = 0; sub < 2; ++sub) {
        const int qblk = (sub == 0) ? (int)blockIdx.x
                                    : (Sdim / 64 - 1 - (int)blockIdx.x);
        const int q0 = qblk * 64;
        const int nt = qblk + 1;
        const int qg = q0 + wid * 16 + g;
        const __half* Q = g_q + (mb0 + q0) * Cdim + h * HD;

        // ---- stage Q through K buffer, load fragments
#pragma unroll
        for (int i2 = 0; i2 < 4; ++i2) {
            const int e = i2 * 128 + tid;
            const int row = e >> 3, ch = e & 7;
            CP_ASYNC16(kb + (uint32_t)(ch * 1024 + row * 16),
                       Q + (size_t)row * Cdim + ch * 8);
        }
        CP_COMMIT(); CP_WAIT(0);
        __syncthreads();

        uint32_t qf[4][4];
        {
            const int qrow = wid * 16 + (lane & 15);
#pragma unroll
            for (int ks = 0; ks < 4; ++ks)
                ldsm_x4(qf[ks], kb + (uint32_t)((2 * ks + (lane >> 4)) * 1024 + qrow * 16));
        }
        __syncthreads();

        float oacc[8][4];
#pragma unroll
        for (int j = 0; j < 8; ++j)
#pragma unroll
            for (int c = 0; c < 4; ++c) oacc[j][c] = 0.f;
        float m0 = -1e30f, m1 = -1e30f, l0 = 0.f, l1 = 0.f;

        load_k(0);

        for (int it = 0; it < nt; ++it) {
            const int k0 = it * 64;

            CP_WAIT(0);                      // K_it resident
            if (tid < 64)
                maskadd[tid] = mrow[k0 + tid] ? -1e30f : 0.f;
            __syncthreads();
            load_v(k0);                      // V_it loads under S compute

            float sacc[8][4];
#pragma unroll
            for (int j = 0; j < 8; ++j)
#pragma unroll
                for (int c = 0; c < 4; ++c) sacc[j][c] = 0.f;

#pragma unroll
            for (int ks = 0; ks < 4; ++ks) {
                uint32_t kf[8][2];
#pragma unroll
                for (int grp = 0; grp < 4; ++grp) {
                    const uint32_t a = (uint32_t)((2 * ks + (lane >> 4)) * 1024 +
                                                  (grp * 16 + (lane & 15)) * 16);
                    uint32_t r[4];
                    ldsm_x4(r, kb + a);
                    kf[2*grp][0] = r[0]; kf[2*grp][1] = r[2];
                    kf[2*grp+1][0] = r[1]; kf[2*grp+1][1] = r[3];
                }
#pragma unroll
                for (int j = 0; j < 8; ++j)
                    mma_f16(sacc[j], qf[ks], kf[j]);
            }

            const bool diag = (k0 == q0);
            float mx0 = -1e30f, mx1 = -1e30f;
#pragma unroll
            for (int j = 0; j < 8; ++j) {
                const float2 ma = *(const float2*)&maskadd[8 * j + 2 * t];
                float s0 = sacc[j][0] + ma.x;
                float s1 = sacc[j][1] + ma.y;
                float s2 = sacc[j][2] + ma.x;
                float s3 = sacc[j][3] + ma.y;
                if (diag) {
                    const int key = k0 + 8 * j + 2 * t;
                    if (key     > qg)     s0 = -1e30f;
                    if (key + 1 > qg)     s1 = -1e30f;
                    if (key     > qg + 8) s2 = -1e30f;
                    if (key + 1 > qg + 8) s3 = -1e30f;
                }
                sacc[j][0] = s0; sacc[j][1] = s1; sacc[j][2] = s2; sacc[j][3] = s3;
                mx0 = fmaxf(mx0, fmaxf(s0, s1));
                mx1 = fmaxf(mx1, fmaxf(s2, s3));
            }
            mx0 = fmaxf(mx0, __shfl_xor_sync(0xFFFFFFFFu, mx0, 1));
            mx0 = fmaxf(mx0, __shfl_xor_sync(0xFFFFFFFFu, mx0, 2));
            mx1 = fmaxf(mx1, __shfl_xor_sync(0xFFFFFFFFu, mx1, 1));
            mx1 = fmaxf(mx1, __shfl_xor_sync(0xFFFFFFFFu, mx1, 2));
            const float mn0 = fmaxf(m0, mx0), mn1 = fmaxf(m1, mx1);
            const float cr0 = fast_exp(m0 - mn0), cr1 = fast_exp(m1 - mn1);
            m0 = mn0; m1 = mn1;
            l0 *= cr0; l1 *= cr1;
#pragma unroll
            for (int j = 0; j < 8; ++j) {
                oacc[j][0] *= cr0; oacc[j][1] *= cr0;
                oacc[j][2] *= cr1; oacc[j][3] *= cr1;
            }

            float sum0 = 0.f, sum1 = 0.f;
            uint32_t pf[4][4];
#pragma unroll
            for (int j = 0; j < 8; ++j) {
                const float p0 = fast_exp(sacc[j][0] - mn0);
                const float p1 = fast_exp(sacc[j][1] - mn0);
                const float p2 = fast_exp(sacc[j][2] - mn1);
                const float p3 = fast_exp(sacc[j][3] - mn1);
                sum0 += p0 + p1; sum1 += p2 + p3;
                const int kk = j >> 1, sl = (j & 1) * 2;
                pf[kk][sl + 0] = pack_f16x2(p0, p1);
                pf[kk][sl + 1] = pack_f16x2(p2, p3);
            }
            sum0 += __shfl_xor_sync(0xFFFFFFFFu, sum0, 1);
            sum0 += __shfl_xor_sync(0xFFFFFFFFu, sum0, 2);
            sum1 += __shfl_xor_sync(0xFFFFFFFFu, sum1, 1);
            sum1 += __shfl_xor_sync(0xFFFFFFFFu, sum1, 2);
            l0 += sum0; l1 += sum1;

            CP_WAIT(0);                      // V_it resident
            __syncthreads();
            if (it + 1 < nt) load_k(k0 + 64);

#pragma unroll
            for (int kp = 0; kp < 4; ++kp) {
                uint32_t vf[8][2];
#pragma unroll
                for (int db = 0; db < 4; ++db) {
                    const uint32_t a = (uint32_t)((2 * db + (lane >> 4)) * 1024 +
                                                  (kp * 16 + (lane & 15)) * 16);
                    uint32_t r[4];
                    ldsm_x4t(r, vb + a);
                    vf[2*db][0] = r[0]; vf[2*db][1] = r[1];
                    vf[2*db+1][0] = r[2]; vf[2*db+1][1] = r[3];
                }
#pragma unroll
                for (int j = 0; j < 8; ++j)
                    mma_f16(oacc[j], pf[kp], vf[j]);
            }
        }

        const float inv0 = 1.f / l0;
        const float inv1 = 1.f / l1;
        __half* o0p = g_at + (mb0 + qg) * Cdim + h * HD;
        __half* o1p = o0p + 8 * Cdim;
#pragma unroll
        for (int j = 0; j < 8; ++j) {
            const int d = 8 * j + 2 * t;
            *(uint32_t*)(o0p + d) = pack_f16x2(oacc[j][0] * inv0, oacc[j][1] * inv0);
            *(uint32_t*)(o1p + d) = pack_f16x2(oacc[j][2] * inv1, oacc[j][3] * inv1);
        }
        __syncthreads();   // buffer reuse safety across sub iterations
    }
}

// ---------------------------------------------------------------------------
extern "C" void kernel_launch(void* const* d_in, const int* in_sizes, int n_in,
                              void* d_out, int out_size)
{
    const float* x     = (const float*)d_in[0];
    const float* y     = (const float*)d_in[1];
    const unsigned char* mask = (const unsigned char*)d_in[2];
    const float* Wq_b  = (const float*)d_in[4];
    const float* Wkv_b = (const float*)d_in[6];
    const float* Wo_b  = (const float*)d_in[8];
    float* out = (float*)d_out;

    convert_all<<<NTOT16 / 256, 256>>>((const float4*)x, (const float4*)y,
                                       (const float4*)d_in[3], (const float4*)d_in[5],
                                       (const float4*)d_in[7]);
    gemm_qkv<<<dim3(8, 64, 3), 256>>>(Wq_b, Wkv_b);
    attn_tc<<<dim3(Sdim / 128, NH, Bdim), 128>>>(mask);
    gemm_o<<<dim3(8, 64), 256>>>(Wo_b, out);
}